// round 11
// baseline (speedup 1.0000x reference)
#include <cuda_runtime.h>
#include <math.h>
#include <stdint.h>

#define DIMS   768
#define HEADS  8
#define HD     96
#define SEQL   2048
#define BATCH  2
#define NROWS  (BATCH*SEQL)   // 4096

// ---------------------------------------------------------------------------
// Scratch (static device globals: allocation-free, graph-capture safe)
// ---------------------------------------------------------------------------
__device__ float    g_q  [NROWS*DIMS];
__device__ float    g_k  [NROWS*DIMS];
__device__ float    g_v  [NROWS*DIMS];
__device__ float    g_att[NROWS*DIMS];
__device__ uint32_t g_vt [BATCH*HEADS*HD*SEQL];   // V^T, tf32 bits
__device__ float    g_wq [DIMS*DIMS];
__device__ float    g_wk [DIMS*DIMS];
__device__ float    g_wv [DIMS*DIMS];
__device__ float    g_wo [DIMS*DIMS];

// ---------------------------------------------------------------------------
// PTX helpers
// ---------------------------------------------------------------------------
__device__ __forceinline__ uint32_t smem_u32(const void* p) {
    uint32_t a;
    asm("{ .reg .u64 t; cvta.to.shared.u64 t, %1; cvt.u32.u64 %0, t; }" : "=r"(a) : "l"(p));
    return a;
}
__device__ __forceinline__ void cp_async16(uint32_t dst, const void* src) {
    asm volatile("cp.async.cg.shared.global [%0], [%1], 16;" :: "r"(dst), "l"(src));
}
__device__ __forceinline__ void cp_async_commit() { asm volatile("cp.async.commit_group;" ::: "memory"); }
template<int N>
__device__ __forceinline__ void cp_async_wait() { asm volatile("cp.async.wait_group %0;" :: "n"(N) : "memory"); }

__device__ __forceinline__ uint32_t f2tf32(float x) {
    uint32_t u;
    asm("cvt.rna.tf32.f32 %0, %1;" : "=r"(u) : "f"(x));
    return u;
}
__device__ __forceinline__ void mma_tf32(float& c0, float& c1, float& c2, float& c3,
                                         uint32_t a0, uint32_t a1, uint32_t a2, uint32_t a3,
                                         uint32_t b0, uint32_t b1) {
    asm volatile(
        "mma.sync.aligned.m16n8k8.row.col.f32.tf32.tf32.f32 "
        "{%0,%1,%2,%3}, {%4,%5,%6,%7}, {%8,%9}, {%0,%1,%2,%3};"
        : "+f"(c0), "+f"(c1), "+f"(c2), "+f"(c3)
        : "r"(a0), "r"(a1), "r"(a2), "r"(a3), "r"(b0), "r"(b1));
}

// ---------------------------------------------------------------------------
// tf32 pre-rounding of the 4 weight matrices
// ---------------------------------------------------------------------------
__device__ __forceinline__ float4 round4(float4 x) {
    return make_float4(__uint_as_float(f2tf32(x.x)), __uint_as_float(f2tf32(x.y)),
                       __uint_as_float(f2tf32(x.z)), __uint_as_float(f2tf32(x.w)));
}
__global__ __launch_bounds__(256)
void round_weights_kernel(const float* __restrict__ a, const float* __restrict__ b,
                          const float* __restrict__ c, const float* __restrict__ d,
                          float* __restrict__ oa, float* __restrict__ ob,
                          float* __restrict__ oc, float* __restrict__ od)
{
    const float* src; float* dst;
    if      (blockIdx.y == 0) { src = a; dst = oa; }
    else if (blockIdx.y == 1) { src = b; dst = ob; }
    else if (blockIdx.y == 2) { src = c; dst = oc; }
    else                      { src = d; dst = od; }
    int i = blockIdx.x * 256 + threadIdx.x;
    ((float4*)dst)[i] = round4(((const float4*)src)[i]);
}

// ---------------------------------------------------------------------------
// NT GEMM via mma.sync tf32 (unchanged from R9).
// ---------------------------------------------------------------------------
#define TM   128
#define TN   128
#define KCH  32
#define PITCH 36
#define NSTAGE 3
#define STAGE_F (TM * PITCH)
#define GEMM_SMEM_BYTES (2 * NSTAGE * STAGE_F * 4)   // 110592 B

template<bool CVT_A>
__device__ __forceinline__
void gemm_body(const float* __restrict__ A, const float* __restrict__ B,
               float* __restrict__ C, int M, int N, int K, float* smem)
{
    float* sA = smem;
    float* sB = smem + NSTAGE * STAGE_F;

    const int tid  = threadIdx.x;
    const int wid  = tid >> 5;
    const int lane = tid & 31;
    const int grp  = lane >> 2;
    const int thr  = lane & 3;
    const int wm   = (wid & 3) * 32;
    const int wn   = (wid >> 2) * 64;
    const int rowBase = blockIdx.x * TM;
    const int colBase = blockIdx.y * TN;

    const uint32_t sA_u = smem_u32(sA);
    const uint32_t sB_u = smem_u32(sB);

    float acc[2][8][4];
#pragma unroll
    for (int mt = 0; mt < 2; mt++)
#pragma unroll
        for (int nt = 0; nt < 8; nt++)
#pragma unroll
            for (int i = 0; i < 4; i++) acc[mt][nt][i] = 0.f;

    const int nChunks = K / KCH;

#define PREFETCH(ch)                                                            \
    do {                                                                        \
        int _k0 = (ch) * KCH;                                                   \
        uint32_t _dA = sA_u + ((ch) % NSTAGE) * STAGE_F * 4;                    \
        uint32_t _dB = sB_u + ((ch) % NSTAGE) * STAGE_F * 4;                    \
        _Pragma("unroll")                                                       \
        for (int _it = 0; _it < 4; _it++) {                                     \
            int _idx = tid + _it * 256;                                         \
            int _r = _idx >> 3, _seg = _idx & 7;                                \
            cp_async16(_dA + (_r * PITCH + _seg * 4) * 4,                       \
                       A + (size_t)(rowBase + _r) * K + _k0 + _seg * 4);        \
            cp_async16(_dB + (_r * PITCH + _seg * 4) * 4,                       \
                       B + (size_t)(colBase + _r) * K + _k0 + _seg * 4);        \
        }                                                                       \
        cp_async_commit();                                                      \
    } while (0)

    PREFETCH(0);
    PREFETCH(1);

    for (int ch = 0; ch < nChunks; ch++) {
        if      (ch + 2 < nChunks) { PREFETCH(ch + 2); cp_async_wait<2>(); }
        else if (ch + 1 < nChunks) { cp_async_wait<1>(); }
        else                       { cp_async_wait<0>(); }
        __syncthreads();

        const float* cA = sA + (ch % NSTAGE) * STAGE_F;
        const float* cB = sB + (ch % NSTAGE) * STAGE_F;

#pragma unroll
        for (int ks = 0; ks < 4; ks++) {
            const int kk = ks * 8;
            uint32_t af[2][4];
#pragma unroll
            for (int mt = 0; mt < 2; mt++) {
                int rb = wm + mt * 16 + grp;
                float a0 = cA[(rb    ) * PITCH + kk + thr    ];
                float a1 = cA[(rb + 8) * PITCH + kk + thr    ];
                float a2 = cA[(rb    ) * PITCH + kk + thr + 4];
                float a3 = cA[(rb + 8) * PITCH + kk + thr + 4];
                if (CVT_A) {
                    af[mt][0] = f2tf32(a0); af[mt][1] = f2tf32(a1);
                    af[mt][2] = f2tf32(a2); af[mt][3] = f2tf32(a3);
                } else {
                    af[mt][0] = __float_as_uint(a0); af[mt][1] = __float_as_uint(a1);
                    af[mt][2] = __float_as_uint(a2); af[mt][3] = __float_as_uint(a3);
                }
            }
            uint32_t bf[8][2];
#pragma unroll
            for (int nt = 0; nt < 8; nt++) {
                int cb = wn + nt * 8 + grp;
                bf[nt][0] = __float_as_uint(cB[cb * PITCH + kk + thr    ]);
                bf[nt][1] = __float_as_uint(cB[cb * PITCH + kk + thr + 4]);
            }
#pragma unroll
            for (int mt = 0; mt < 2; mt++)
#pragma unroll
                for (int nt = 0; nt < 8; nt++)
                    mma_tf32(acc[mt][nt][0], acc[mt][nt][1],
                             acc[mt][nt][2], acc[mt][nt][3],
                             af[mt][0], af[mt][1], af[mt][2], af[mt][3],
                             bf[nt][0], bf[nt][1]);
        }
        __syncthreads();
    }
#undef PREFETCH

#pragma unroll
    for (int mt = 0; mt < 2; mt++) {
        int r0 = rowBase + wm + mt * 16 + grp;
#pragma unroll
        for (int nt = 0; nt < 8; nt++) {
            int c0 = colBase + wn + nt * 8 + thr * 2;
            float2* p0 = (float2*)(C + (size_t)r0 * N + c0);
            float2* p1 = (float2*)(C + (size_t)(r0 + 8) * N + c0);
            *p0 = make_float2(acc[mt][nt][0], acc[mt][nt][1]);
            *p1 = make_float2(acc[mt][nt][2], acc[mt][nt][3]);
        }
    }
}

__global__ __launch_bounds__(256)
void gemm_qkv_kernel(const float* __restrict__ Qin, const float* __restrict__ Kin,
                     const float* __restrict__ Vin, const float* __restrict__ Wq,
                     const float* __restrict__ Wk, const float* __restrict__ Wv,
                     float* __restrict__ q, float* __restrict__ k, float* __restrict__ v)
{
    extern __shared__ float smem[];
    const float *A, *B;
    float* C;
    if      (blockIdx.z == 0) { A = Qin; B = Wq; C = q; }
    else if (blockIdx.z == 1) { A = Kin; B = Wk; C = k; }
    else                      { A = Vin; B = Wv; C = v; }
    gemm_body<true>(A, B, C, NROWS, DIMS, DIMS, smem);
}

__global__ __launch_bounds__(256)
void gemm_wo_kernel(const float* __restrict__ A, const float* __restrict__ B,
                    float* __restrict__ C)
{
    extern __shared__ float smem[];
    gemm_body<false>(A, B, C, NROWS, DIMS, DIMS, smem);
}

// ---------------------------------------------------------------------------
// Fused pointwise stage: z=0 rope(q), z=1 rope(k), z=2 transpose(v)->vt.
// ---------------------------------------------------------------------------
#define ROPE_BLOCKS ((NROWS * HEADS * 48) / 256)     // 6144
#define TRANS_BLOCKS ((DIMS / 32) * (NROWS / 32))    // 3072

__global__ __launch_bounds__(256)
void pointwise_kernel(float* __restrict__ xq, const float* __restrict__ cq,
                      float* __restrict__ xk, const float* __restrict__ ck,
                      const float* __restrict__ v, uint32_t* __restrict__ vt)
{
    __shared__ float t[32][33];
    const int z = blockIdx.y;

    if (z < 2) {
        float* x            = z ? xk : xq;
        const float* coords = z ? ck : cq;

        int idx = blockIdx.x * 256 + threadIdx.x;
        int p  = idx % 48;
        int h  = (idx / 48) % HEADS;
        int bl = idx / (48 * HEADS);
        int axis = p >> 4;
        int j    = p & 15;

        float coord = coords[(size_t)bl * 3 + axis];
        float inv = exp2f(-(float)j * (0.0625f * 13.28771238f));  // log2(1e4)/16
        float ang = coord * inv;
        float s, c;
        sincosf(ang, &s, &c);

        float* base = x + (size_t)bl * DIMS + h * HD + axis * 32;
        float x1 = base[j];
        float x2 = base[j + 16];
        base[j]      = __uint_as_float(f2tf32(x1 * c - x2 * s));
        base[j + 16] = __uint_as_float(f2tf32(x1 * s + x2 * c));
    } else {
        if (blockIdx.x >= TRANS_BLOCKS) return;
        const int tx = threadIdx.x & 31;
        const int ty = threadIdx.x >> 5;
        const int c0 = (blockIdx.x % (DIMS / 32)) * 32;
        const int r0 = (blockIdx.x / (DIMS / 32)) * 32;

#pragma unroll
        for (int i = 0; i < 4; i++)
            t[ty + i * 8][tx] = v[(size_t)(r0 + ty + i * 8) * DIMS + c0 + tx];
        __syncthreads();

#pragma unroll
        for (int i = 0; i < 4; i++) {
            int c = c0 + ty + i * 8;
            int h = c / HD, d = c % HD;
            int b = r0 >> 11, tl = r0 & 2047;
            vt[((size_t)(b * HEADS + h) * HD + d) * SEQL + tl + tx] =
                f2tf32(t[tx][ty + i * 8]);
        }
    }
}

// ---------------------------------------------------------------------------
// Flash attention, mma.sync tf32. BQ=64, BK=64, 256 threads (8 warps).
// KEY SPLIT: warps 0-3 handle keys 0-31 of each tile, warps 4-7 keys 32-63;
// each group keeps its own online-softmax state; merged once at the end.
// Same smem as R9 (94.7KB) -> 2 CTAs/SM, 16 warps/SM (2x occupancy).
// ---------------------------------------------------------------------------
#define BQ 64
#define BK 64
#define QP 100
#define VP 68
#define ATTN_SMEM_U32 (BQ*QP + BK*QP + HD*VP + BQ*VP)       // 23680
#define ATTN_SMEM_BYTES (ATTN_SMEM_U32 * 4)                 // 94720
#define MRG_PITCH 104

__global__ __launch_bounds__(256)
void attn_mma_kernel(const float* __restrict__ q, const float* __restrict__ k,
                     const uint32_t* __restrict__ vt, float* __restrict__ O)
{
    extern __shared__ uint32_t smu[];
    uint32_t* sQ  = smu;
    uint32_t* sK  = sQ + BQ * QP;
    uint32_t* sVT = sK + BK * QP;
    uint32_t* sP  = sVT + HD * VP;

    const int tid  = threadIdx.x;
    const int wid  = tid >> 5;
    const int lane = tid & 31;
    const int grp  = lane >> 2;
    const int thr  = lane & 3;
    const int wr   = (wid & 3) * 16;    // query-row base (shared by warp pairs)
    const int kg   = wid >> 2;          // key group: 0 -> keys 0-31, 1 -> 32-63
    const int ng0  = kg * 32;           // S-column / PV-k base for this group
    const int q0   = blockIdx.x * BQ;
    const int h    = blockIdx.y;
    const int b    = blockIdx.z;

    const uint32_t sQ_u  = smem_u32(sQ);
    const uint32_t sK_u  = smem_u32(sK);
    const uint32_t sVT_u = smem_u32(sVT);

    const float scale = rsqrtf((float)HD);

    const float*    Qb = q  + ((size_t)b * SEQL + q0) * DIMS + h * HD;
    const float*    Kb = k  + (size_t)b * SEQL * DIMS + h * HD;
    const uint32_t* Vb = vt + (size_t)(b * HEADS + h) * HD * SEQL;

    // Q tile: 64 rows x 24 16B-chunks = 1536, 256 threads -> 6 iters
#pragma unroll
    for (int i = 0; i < 6; i++) {
        int idx = tid + i * 256;
        int r = idx / 24, c4 = idx % 24;
        cp_async16(sQ_u + (r * QP + c4 * 4) * 4, Qb + (size_t)r * DIMS + c4 * 4);
    }
    cp_async_commit();

    float m0 = -1e30f, m1 = -1e30f, l0 = 0.f, l1 = 0.f;
    float o[12][4];
#pragma unroll
    for (int nt = 0; nt < 12; nt++)
#pragma unroll
        for (int i = 0; i < 4; i++) o[nt][i] = 0.f;

    for (int kb = 0; kb < SEQL / BK; kb++) {
        const int k0 = kb * BK;
        __syncthreads();
#pragma unroll
        for (int i = 0; i < 6; i++) {
            int idx = tid + i * 256;
            int r = idx / 24, c4 = idx % 24;
            cp_async16(sK_u + (r * QP + c4 * 4) * 4,
                       Kb + (size_t)(k0 + r) * DIMS + c4 * 4);
        }
#pragma unroll
        for (int i = 0; i < 6; i++) {
            int idx = tid + i * 256;
            int d = idx / 16, c4 = idx % 16;
            cp_async16(sVT_u + (d * VP + c4 * 4) * 4,
                       Vb + (size_t)d * SEQL + k0 + c4 * 4);
        }
        cp_async_commit();
        cp_async_wait<0>();
        __syncthreads();

        // ---- S = Q K^T (warp: 16 q-rows x 32 keys of its group) ----
        float s[4][4];
#pragma unroll
        for (int nt = 0; nt < 4; nt++)
#pragma unroll
            for (int i = 0; i < 4; i++) s[nt][i] = 0.f;

#pragma unroll
        for (int ks = 0; ks < 12; ks++) {
            const int kk = ks * 8;
            uint32_t a0 = sQ[(wr + grp    ) * QP + kk + thr    ];
            uint32_t a1 = sQ[(wr + grp + 8) * QP + kk + thr    ];
            uint32_t a2 = sQ[(wr + grp    ) * QP + kk + thr + 4];
            uint32_t a3 = sQ[(wr + grp + 8) * QP + kk + thr + 4];
#pragma unroll
            for (int nt = 0; nt < 4; nt++) {
                uint32_t b0 = sK[(ng0 + nt * 8 + grp) * QP + kk + thr    ];
                uint32_t b1 = sK[(ng0 + nt * 8 + grp) * QP + kk + thr + 4];
                mma_tf32(s[nt][0], s[nt][1], s[nt][2], s[nt][3],
                         a0, a1, a2, a3, b0, b1);
            }
        }

        // ---- online softmax over this group's 32 keys ----
        float mt0 = -1e30f, mt1 = -1e30f;
#pragma unroll
        for (int nt = 0; nt < 4; nt++) {
#pragma unroll
            for (int i = 0; i < 4; i++) s[nt][i] *= scale;
            mt0 = fmaxf(mt0, fmaxf(s[nt][0], s[nt][1]));
            mt1 = fmaxf(mt1, fmaxf(s[nt][2], s[nt][3]));
        }
        mt0 = fmaxf(mt0, __shfl_xor_sync(0xffffffffu, mt0, 1));
        mt0 = fmaxf(mt0, __shfl_xor_sync(0xffffffffu, mt0, 2));
        mt1 = fmaxf(mt1, __shfl_xor_sync(0xffffffffu, mt1, 1));
        mt1 = fmaxf(mt1, __shfl_xor_sync(0xffffffffu, mt1, 2));

        float mn0 = fmaxf(m0, mt0), mn1 = fmaxf(m1, mt1);
        float al0 = __expf(m0 - mn0), al1 = __expf(m1 - mn1);
        float ls0 = 0.f, ls1 = 0.f;

#pragma unroll
        for (int nt = 0; nt < 4; nt++) {
            float p0 = __expf(s[nt][0] - mn0);
            float p1 = __expf(s[nt][1] - mn0);
            float p2 = __expf(s[nt][2] - mn1);
            float p3 = __expf(s[nt][3] - mn1);
            ls0 += p0 + p1;
            ls1 += p2 + p3;
            uint2* w0 = (uint2*)&sP[(wr + grp    ) * VP + ng0 + nt * 8 + thr * 2];
            uint2* w1 = (uint2*)&sP[(wr + grp + 8) * VP + ng0 + nt * 8 + thr * 2];
            *w0 = make_uint2(f2tf32(p0), f2tf32(p1));
            *w1 = make_uint2(f2tf32(p2), f2tf32(p3));
        }
        ls0 += __shfl_xor_sync(0xffffffffu, ls0, 1);
        ls0 += __shfl_xor_sync(0xffffffffu, ls0, 2);
        ls1 += __shfl_xor_sync(0xffffffffu, ls1, 1);
        ls1 += __shfl_xor_sync(0xffffffffu, ls1, 2);

        l0 = l0 * al0 + ls0;  m0 = mn0;
        l1 = l1 * al1 + ls1;  m1 = mn1;
#pragma unroll
        for (int nt = 0; nt < 12; nt++) {
            o[nt][0] *= al0; o[nt][1] *= al0;
            o[nt][2] *= al1; o[nt][3] *= al1;
        }
        __syncwarp();

        // ---- O += P V over this group's 32 keys ----
#pragma unroll
        for (int ks = 0; ks < 4; ks++) {
            const int kk = ng0 + ks * 8;
            uint32_t a0 = sP[(wr + grp    ) * VP + kk + thr    ];
            uint32_t a1 = sP[(wr + grp + 8) * VP + kk + thr    ];
            uint32_t a2 = sP[(wr + grp    ) * VP + kk + thr + 4];
            uint32_t a3 = sP[(wr + grp + 8) * VP + kk + thr + 4];
#pragma unroll
            for (int nt = 0; nt < 12; nt++) {
                uint32_t b0 = sVT[(nt * 8 + grp) * VP + kk + thr    ];
                uint32_t b1 = sVT[(nt * 8 + grp) * VP + kk + thr + 4];
                mma_tf32(o[nt][0], o[nt][1], o[nt][2], o[nt][3],
                         a0, a1, a2, a3, b0, b1);
            }
        }
    }

    // ---- merge the two key groups (reuse sQ/sK region as scratch) ----
    __syncthreads();
    float* sm = (float*)smu;   // m[64], l[64], o[64][MRG_PITCH]
    const int r0 = wr + grp, r1 = wr + grp + 8;

    if (kg == 1) {
        if (thr == 0) {
            sm[r0] = m0; sm[64 + r0] = l0;
            sm[r1] = m1; sm[64 + r1] = l1;
        }
#pragma unroll
        for (int nt = 0; nt < 12; nt++) {
            *(float2*)&sm[128 + r0 * MRG_PITCH + nt * 8 + thr * 2] =
                make_float2(o[nt][0], o[nt][1]);
            *(float2*)&sm[128 + r1 * MRG_PITCH + nt * 8 + thr * 2] =
                make_float2(o[nt][2], o[nt][3]);
        }
    }
    __syncthreads();

    if (kg == 0) {
        float mB0 = sm[r0], lB0 = sm[64 + r0];
        float mB1 = sm[r1], lB1 = sm[64 + r1];
        float mn0 = fmaxf(m0, mB0), mn1 = fmaxf(m1, mB1);
        float aA0 = __expf(m0 - mn0), aB0 = __expf(mB0 - mn0);
        float aA1 = __expf(m1 - mn1), aB1 = __expf(mB1 - mn1);
        float inv0 = 1.f / (l0 * aA0 + lB0 * aB0);
        float inv1 = 1.f / (l1 * aA1 + lB1 * aB1);

        size_t row0 = ((size_t)b * SEQL + q0 + r0) * DIMS + h * HD;
        size_t row1 = ((size_t)b * SEQL + q0 + r1) * DIMS + h * HD;
#pragma unroll
        for (int nt = 0; nt < 12; nt++) {
            float2 ob0 = *(float2*)&sm[128 + r0 * MRG_PITCH + nt * 8 + thr * 2];
            float2 ob1 = *(float2*)&sm[128 + r1 * MRG_PITCH + nt * 8 + thr * 2];
            int c = nt * 8 + thr * 2;
            *(float2*)(O + row0 + c) = make_float2(
                __uint_as_float(f2tf32((o[nt][0] * aA0 + ob0.x * aB0) * inv0)),
                __uint_as_float(f2tf32((o[nt][1] * aA0 + ob0.y * aB0) * inv0)));
            *(float2*)(O + row1 + c) = make_float2(
                __uint_as_float(f2tf32((o[nt][2] * aA1 + ob1.x * aB1) * inv1)),
                __uint_as_float(f2tf32((o[nt][3] * aA1 + ob1.y * aB1) * inv1)));
        }
    }
}

// ---------------------------------------------------------------------------
// Launch
// ---------------------------------------------------------------------------
extern "C" void kernel_launch(void* const* d_in, const int* in_sizes, int n_in,
                              void* d_out, int out_size)
{
    const float* Q_in = (const float*)d_in[0];
    const float* K_in = (const float*)d_in[1];
    const float* V_in = (const float*)d_in[2];
    const float* cq   = (const float*)d_in[3];
    const float* ck   = (const float*)d_in[4];
    const float* Wq   = (const float*)d_in[5];
    const float* Wk   = (const float*)d_in[6];
    const float* Wv   = (const float*)d_in[7];
    const float* Wo   = (const float*)d_in[8];
    float* out = (float*)d_out;

    float *q, *k, *v, *att, *wq, *wk, *wv, *wo;
    uint32_t* vt;
    cudaGetSymbolAddress((void**)&q,   g_q);
    cudaGetSymbolAddress((void**)&k,   g_k);
    cudaGetSymbolAddress((void**)&v,   g_v);
    cudaGetSymbolAddress((void**)&att, g_att);
    cudaGetSymbolAddress((void**)&vt,  g_vt);
    cudaGetSymbolAddress((void**)&wq,  g_wq);
    cudaGetSymbolAddress((void**)&wk,  g_wk);
    cudaGetSymbolAddress((void**)&wv,  g_wv);
    cudaGetSymbolAddress((void**)&wo,  g_wo);

    cudaFuncSetAttribute(gemm_qkv_kernel, cudaFuncAttributeMaxDynamicSharedMemorySize,
                         GEMM_SMEM_BYTES);
    cudaFuncSetAttribute(gemm_wo_kernel, cudaFuncAttributeMaxDynamicSharedMemorySize,
                         GEMM_SMEM_BYTES);
    cudaFuncSetAttribute(attn_mma_kernel, cudaFuncAttributeMaxDynamicSharedMemorySize,
                         ATTN_SMEM_BYTES);

    round_weights_kernel<<<dim3(DIMS * DIMS / 4 / 256, 4), 256>>>(
        Wq, Wk, Wv, Wo, wq, wk, wv, wo);

    gemm_qkv_kernel<<<dim3(NROWS / TM, DIMS / TN, 3), 256, GEMM_SMEM_BYTES>>>(
        Q_in, K_in, V_in, wq, wk, wv, q, k, v);

    pointwise_kernel<<<dim3(ROPE_BLOCKS, 3), 256>>>(q, cq, k, ck, v, vt);

    attn_mma_kernel<<<dim3(SEQL / BQ, HEADS, BATCH), 256, ATTN_SMEM_BYTES>>>(q, k, vt, att);

    gemm_wo_kernel<<<dim3(NROWS / TM, DIMS / TN), 256, GEMM_SMEM_BYTES>>>(att, wo, out);
}

// round 12
// speedup vs baseline: 1.1392x; 1.1392x over previous
#include <cuda_runtime.h>
#include <math.h>
#include <stdint.h>

#define DIMS   768
#define HEADS  8
#define HD     96
#define SEQL   2048
#define BATCH  2
#define NROWS  (BATCH*SEQL)   // 4096

// ---------------------------------------------------------------------------
// Scratch (static device globals)
// ---------------------------------------------------------------------------
__device__ float    g_q  [NROWS*DIMS];
__device__ float    g_k  [NROWS*DIMS];
__device__ float    g_v  [NROWS*DIMS];
__device__ float    g_q2 [NROWS*DIMS];            // rope(q), k-permuted layout
__device__ float    g_k2 [NROWS*DIMS];            // rope(k), k-permuted layout
__device__ float    g_att[NROWS*DIMS];
__device__ uint32_t g_vt [BATCH*HEADS*HD*SEQL];   // V^T, tf32 bits, token-permuted
__device__ float    g_wq [DIMS*DIMS];
__device__ float    g_wk [DIMS*DIMS];
__device__ float    g_wv [DIMS*DIMS];
__device__ float    g_wo [DIMS*DIMS];

// ---------------------------------------------------------------------------
// PTX helpers
// ---------------------------------------------------------------------------
__device__ __forceinline__ uint32_t smem_u32(const void* p) {
    uint32_t a;
    asm("{ .reg .u64 t; cvta.to.shared.u64 t, %1; cvt.u32.u64 %0, t; }" : "=r"(a) : "l"(p));
    return a;
}
__device__ __forceinline__ void cp_async16(uint32_t dst, const void* src) {
    asm volatile("cp.async.cg.shared.global [%0], [%1], 16;" :: "r"(dst), "l"(src));
}
__device__ __forceinline__ void cp_async_commit() { asm volatile("cp.async.commit_group;" ::: "memory"); }
template<int N>
__device__ __forceinline__ void cp_async_wait() { asm volatile("cp.async.wait_group %0;" :: "n"(N) : "memory"); }

__device__ __forceinline__ uint32_t f2tf32(float x) {
    uint32_t u;
    asm("cvt.rna.tf32.f32 %0, %1;" : "=r"(u) : "f"(x));
    return u;
}
__device__ __forceinline__ void mma_tf32(float& c0, float& c1, float& c2, float& c3,
                                         uint32_t a0, uint32_t a1, uint32_t a2, uint32_t a3,
                                         uint32_t b0, uint32_t b1) {
    asm volatile(
        "mma.sync.aligned.m16n8k8.row.col.f32.tf32.tf32.f32 "
        "{%0,%1,%2,%3}, {%4,%5,%6,%7}, {%8,%9}, {%0,%1,%2,%3};"
        : "+f"(c0), "+f"(c1), "+f"(c2), "+f"(c3)
        : "r"(a0), "r"(a1), "r"(a2), "r"(a3), "r"(b0), "r"(b1));
}

// k-group permutation: within each 8-element group, r -> 2*(r%4) + r/4.
// Makes fragment pair (thr, thr+4) adjacent -> one 64-bit LDS.
__device__ __forceinline__ int perm8(int c) {
    return (c & ~7) | (((c & 3) << 1) | ((c >> 2) & 1));
}

// ---------------------------------------------------------------------------
// tf32 pre-rounding of the 4 weight matrices
// ---------------------------------------------------------------------------
__device__ __forceinline__ float4 round4(float4 x) {
    return make_float4(__uint_as_float(f2tf32(x.x)), __uint_as_float(f2tf32(x.y)),
                       __uint_as_float(f2tf32(x.z)), __uint_as_float(f2tf32(x.w)));
}
__global__ __launch_bounds__(256)
void round_weights_kernel(const float* __restrict__ a, const float* __restrict__ b,
                          const float* __restrict__ c, const float* __restrict__ d,
                          float* __restrict__ oa, float* __restrict__ ob,
                          float* __restrict__ oc, float* __restrict__ od)
{
    const float* src; float* dst;
    if      (blockIdx.y == 0) { src = a; dst = oa; }
    else if (blockIdx.y == 1) { src = b; dst = ob; }
    else if (blockIdx.y == 2) { src = c; dst = oc; }
    else                      { src = d; dst = od; }
    int i = blockIdx.x * 256 + threadIdx.x;
    ((float4*)dst)[i] = round4(((const float4*)src)[i]);
}

// ---------------------------------------------------------------------------
// NT GEMM via mma.sync tf32 (unchanged from R9).
// ---------------------------------------------------------------------------
#define TM   128
#define TN   128
#define KCH  32
#define PITCH 36
#define NSTAGE 3
#define STAGE_F (TM * PITCH)
#define GEMM_SMEM_BYTES (2 * NSTAGE * STAGE_F * 4)   // 110592 B

template<bool CVT_A>
__device__ __forceinline__
void gemm_body(const float* __restrict__ A, const float* __restrict__ B,
               float* __restrict__ C, int M, int N, int K, float* smem)
{
    float* sA = smem;
    float* sB = smem + NSTAGE * STAGE_F;

    const int tid  = threadIdx.x;
    const int wid  = tid >> 5;
    const int lane = tid & 31;
    const int grp  = lane >> 2;
    const int thr  = lane & 3;
    const int wm   = (wid & 3) * 32;
    const int wn   = (wid >> 2) * 64;
    const int rowBase = blockIdx.x * TM;
    const int colBase = blockIdx.y * TN;

    const uint32_t sA_u = smem_u32(sA);
    const uint32_t sB_u = smem_u32(sB);

    float acc[2][8][4];
#pragma unroll
    for (int mt = 0; mt < 2; mt++)
#pragma unroll
        for (int nt = 0; nt < 8; nt++)
#pragma unroll
            for (int i = 0; i < 4; i++) acc[mt][nt][i] = 0.f;

    const int nChunks = K / KCH;

#define PREFETCH(ch)                                                            \
    do {                                                                        \
        int _k0 = (ch) * KCH;                                                   \
        uint32_t _dA = sA_u + ((ch) % NSTAGE) * STAGE_F * 4;                    \
        uint32_t _dB = sB_u + ((ch) % NSTAGE) * STAGE_F * 4;                    \
        _Pragma("unroll")                                                       \
        for (int _it = 0; _it < 4; _it++) {                                     \
            int _idx = tid + _it * 256;                                         \
            int _r = _idx >> 3, _seg = _idx & 7;                                \
            cp_async16(_dA + (_r * PITCH + _seg * 4) * 4,                       \
                       A + (size_t)(rowBase + _r) * K + _k0 + _seg * 4);        \
            cp_async16(_dB + (_r * PITCH + _seg * 4) * 4,                       \
                       B + (size_t)(colBase + _r) * K + _k0 + _seg * 4);        \
        }                                                                       \
        cp_async_commit();                                                      \
    } while (0)

    PREFETCH(0);
    PREFETCH(1);

    for (int ch = 0; ch < nChunks; ch++) {
        if      (ch + 2 < nChunks) { PREFETCH(ch + 2); cp_async_wait<2>(); }
        else if (ch + 1 < nChunks) { cp_async_wait<1>(); }
        else                       { cp_async_wait<0>(); }
        __syncthreads();

        const float* cA = sA + (ch % NSTAGE) * STAGE_F;
        const float* cB = sB + (ch % NSTAGE) * STAGE_F;

#pragma unroll
        for (int ks = 0; ks < 4; ks++) {
            const int kk = ks * 8;
            uint32_t af[2][4];
#pragma unroll
            for (int mt = 0; mt < 2; mt++) {
                int rb = wm + mt * 16 + grp;
                float a0 = cA[(rb    ) * PITCH + kk + thr    ];
                float a1 = cA[(rb + 8) * PITCH + kk + thr    ];
                float a2 = cA[(rb    ) * PITCH + kk + thr + 4];
                float a3 = cA[(rb + 8) * PITCH + kk + thr + 4];
                if (CVT_A) {
                    af[mt][0] = f2tf32(a0); af[mt][1] = f2tf32(a1);
                    af[mt][2] = f2tf32(a2); af[mt][3] = f2tf32(a3);
                } else {
                    af[mt][0] = __float_as_uint(a0); af[mt][1] = __float_as_uint(a1);
                    af[mt][2] = __float_as_uint(a2); af[mt][3] = __float_as_uint(a3);
                }
            }
            uint32_t bf[8][2];
#pragma unroll
            for (int nt = 0; nt < 8; nt++) {
                int cb = wn + nt * 8 + grp;
                bf[nt][0] = __float_as_uint(cB[cb * PITCH + kk + thr    ]);
                bf[nt][1] = __float_as_uint(cB[cb * PITCH + kk + thr + 4]);
            }
#pragma unroll
            for (int mt = 0; mt < 2; mt++)
#pragma unroll
                for (int nt = 0; nt < 8; nt++)
                    mma_tf32(acc[mt][nt][0], acc[mt][nt][1],
                             acc[mt][nt][2], acc[mt][nt][3],
                             af[mt][0], af[mt][1], af[mt][2], af[mt][3],
                             bf[nt][0], bf[nt][1]);
        }
        __syncthreads();
    }
#undef PREFETCH

#pragma unroll
    for (int mt = 0; mt < 2; mt++) {
        int r0 = rowBase + wm + mt * 16 + grp;
#pragma unroll
        for (int nt = 0; nt < 8; nt++) {
            int c0 = colBase + wn + nt * 8 + thr * 2;
            float2* p0 = (float2*)(C + (size_t)r0 * N + c0);
            float2* p1 = (float2*)(C + (size_t)(r0 + 8) * N + c0);
            *p0 = make_float2(acc[mt][nt][0], acc[mt][nt][1]);
            *p1 = make_float2(acc[mt][nt][2], acc[mt][nt][3]);
        }
    }
}

__global__ __launch_bounds__(256)
void gemm_qkv_kernel(const float* __restrict__ Qin, const float* __restrict__ Kin,
                     const float* __restrict__ Vin, const float* __restrict__ Wq,
                     const float* __restrict__ Wk, const float* __restrict__ Wv,
                     float* __restrict__ q, float* __restrict__ k, float* __restrict__ v)
{
    extern __shared__ float smem[];
    const float *A, *B;
    float* C;
    if      (blockIdx.z == 0) { A = Qin; B = Wq; C = q; }
    else if (blockIdx.z == 1) { A = Kin; B = Wk; C = k; }
    else                      { A = Vin; B = Wv; C = v; }
    gemm_body<true>(A, B, C, NROWS, DIMS, DIMS, smem);
}

__global__ __launch_bounds__(256)
void gemm_wo_kernel(const float* __restrict__ A, const float* __restrict__ B,
                    float* __restrict__ C)
{
    extern __shared__ float smem[];
    gemm_body<false>(A, B, C, NROWS, DIMS, DIMS, smem);
}

// ---------------------------------------------------------------------------
// Fused pointwise: z=0 rope(q)->q2 (k-permuted), z=1 rope(k)->k2,
// z=2 transpose(v)->vt (token-permuted). All outputs tf32-rounded.
// ---------------------------------------------------------------------------
#define ROPE_BLOCKS ((NROWS * HEADS * 48) / 256)     // 6144
#define TRANS_BLOCKS ((DIMS / 32) * (NROWS / 32))    // 3072

__global__ __launch_bounds__(256)
void pointwise_kernel(const float* __restrict__ xq, float* __restrict__ oq,
                      const float* __restrict__ cq,
                      const float* __restrict__ xk, float* __restrict__ ok,
                      const float* __restrict__ ck,
                      const float* __restrict__ v, uint32_t* __restrict__ vt)
{
    __shared__ float t[32][33];
    const int z = blockIdx.y;

    if (z < 2) {
        const float* x      = z ? xk : xq;
        float* out          = z ? ok : oq;
        const float* coords = z ? ck : cq;

        int idx = blockIdx.x * 256 + threadIdx.x;
        int p  = idx % 48;
        int h  = (idx / 48) % HEADS;
        int bl = idx / (48 * HEADS);
        int axis = p >> 4;
        int j    = p & 15;

        float coord = coords[(size_t)bl * 3 + axis];
        float inv = exp2f(-(float)j * (0.0625f * 13.28771238f));  // log2(1e4)/16
        float ang = coord * inv;
        float s, c;
        sincosf(ang, &s, &c);

        size_t base = (size_t)bl * DIMS + h * HD;
        int c1 = axis * 32 + j;
        int c2 = c1 + 16;
        float x1 = x[base + c1];
        float x2 = x[base + c2];
        out[base + perm8(c1)] = __uint_as_float(f2tf32(x1 * c - x2 * s));
        out[base + perm8(c2)] = __uint_as_float(f2tf32(x1 * s + x2 * c));
    } else {
        if (blockIdx.x >= TRANS_BLOCKS) return;
        const int tx = threadIdx.x & 31;
        const int ty = threadIdx.x >> 5;
        const int c0 = (blockIdx.x % (DIMS / 32)) * 32;
        const int r0 = (blockIdx.x / (DIMS / 32)) * 32;

#pragma unroll
        for (int i = 0; i < 4; i++)
            t[ty + i * 8][tx] = v[(size_t)(r0 + ty + i * 8) * DIMS + c0 + tx];
        __syncthreads();

        int txp = perm8(tx);   // token-permuted position within 32-block
#pragma unroll
        for (int i = 0; i < 4; i++) {
            int c = c0 + ty + i * 8;
            int h = c / HD, d = c % HD;
            int b = r0 >> 11, tl = r0 & 2047;
            vt[((size_t)(b * HEADS + h) * HD + d) * SEQL + tl + txp] =
                f2tf32(t[tx][ty + i * 8]);
        }
    }
}

// ---------------------------------------------------------------------------
// Flash attention, mma.sync tf32. R9 shape: BQ=64, BK=64, 128 threads (4 warps).
// Permuted k-layout -> all fragment loads are 64-bit; Q fragments hoisted to
// registers (loop-invariant). Pitches == 8 mod 32 words -> conflict-free.
// ---------------------------------------------------------------------------
#define BQ 64
#define BK 64
#define QP 104
#define VP 72
#define PP 72
#define ATTN_SMEM_U32 (BQ*QP + BK*QP + HD*VP + BQ*PP)   // 24832
#define ATTN_SMEM_BYTES (ATTN_SMEM_U32 * 4)             // 99328

__global__ __launch_bounds__(128)
void attn_mma_kernel(const float* __restrict__ q, const float* __restrict__ k,
                     const uint32_t* __restrict__ vt, float* __restrict__ O)
{
    extern __shared__ uint32_t smu[];
    uint32_t* sQ  = smu;                     // [64][104]
    uint32_t* sK  = sQ + BQ * QP;            // [64][104]
    uint32_t* sVT = sK + BK * QP;            // [96][72]
    uint32_t* sP  = sVT + HD * VP;           // [64][72]

    const int tid  = threadIdx.x;
    const int wid  = tid >> 5;
    const int lane = tid & 31;
    const int grp  = lane >> 2;
    const int thr  = lane & 3;
    const int wr   = wid * 16;
    const int q0   = blockIdx.x * BQ;
    const int h    = blockIdx.y;
    const int b    = blockIdx.z;

    const uint32_t sQ_u  = smem_u32(sQ);
    const uint32_t sK_u  = smem_u32(sK);
    const uint32_t sVT_u = smem_u32(sVT);

    const float scale = rsqrtf((float)HD);

    const float*    Qb = q  + ((size_t)b * SEQL + q0) * DIMS + h * HD;
    const float*    Kb = k  + (size_t)b * SEQL * DIMS + h * HD;
    const uint32_t* Vb = vt + (size_t)(b * HEADS + h) * HD * SEQL;

    // sP write positions for this thread's two C-columns (permuted)
    const int pp0 = ((2 * thr & 3) << 1) | ((2 * thr) >> 2);
    const int pp1 = (((2 * thr + 1) & 3) << 1) | ((2 * thr + 1) >> 2);

    // Q tile: 64 rows x 24 16B-chunks = 1536
#pragma unroll
    for (int i = 0; i < 12; i++) {
        int idx = tid + i * 128;
        int r = idx / 24, c4 = idx % 24;
        cp_async16(sQ_u + (r * QP + c4 * 4) * 4, Qb + (size_t)r * DIMS + c4 * 4);
    }
    cp_async_commit();
    cp_async_wait<0>();
    __syncthreads();

    // hoist Q fragments (loop-invariant across all key tiles)
    uint2 qf0[12], qf1[12];
#pragma unroll
    for (int ks = 0; ks < 12; ks++) {
        qf0[ks] = *(uint2*)&sQ[(wr + grp    ) * QP + ks * 8 + 2 * thr];  // (a0, a2)
        qf1[ks] = *(uint2*)&sQ[(wr + grp + 8) * QP + ks * 8 + 2 * thr];  // (a1, a3)
    }

    float m0 = -1e30f, m1 = -1e30f, l0 = 0.f, l1 = 0.f;
    float o[12][4];
#pragma unroll
    for (int nt = 0; nt < 12; nt++)
#pragma unroll
        for (int i = 0; i < 4; i++) o[nt][i] = 0.f;

    for (int kb = 0; kb < SEQL / BK; kb++) {
        const int k0 = kb * BK;
        __syncthreads();   // previous iteration done with sK/sVT
#pragma unroll
        for (int i = 0; i < 12; i++) {
            int idx = tid + i * 128;
            int r = idx / 24, c4 = idx % 24;
            cp_async16(sK_u + (r * QP + c4 * 4) * 4,
                       Kb + (size_t)(k0 + r) * DIMS + c4 * 4);
        }
#pragma unroll
        for (int i = 0; i < 12; i++) {
            int idx = tid + i * 128;
            int d = idx / 16, c4 = idx % 16;
            cp_async16(sVT_u + (d * VP + c4 * 4) * 4,
                       Vb + (size_t)d * SEQL + k0 + c4 * 4);
        }
        cp_async_commit();
        cp_async_wait<0>();
        __syncthreads();

        // ---- S = Q K^T (warp: 16 q-rows x 64 keys); 64-bit B loads ----
        float s[8][4];
#pragma unroll
        for (int nt = 0; nt < 8; nt++)
#pragma unroll
            for (int i = 0; i < 4; i++) s[nt][i] = 0.f;

#pragma unroll
        for (int ks = 0; ks < 12; ks++) {
            const int kk = ks * 8 + 2 * thr;
            const uint2 a0 = qf0[ks], a1 = qf1[ks];
#pragma unroll
            for (int nt = 0; nt < 8; nt++) {
                uint2 bb = *(uint2*)&sK[(nt * 8 + grp) * QP + kk];
                mma_tf32(s[nt][0], s[nt][1], s[nt][2], s[nt][3],
                         a0.x, a1.x, a0.y, a1.y, bb.x, bb.y);
            }
        }

        // ---- online softmax (rows grp and grp+8) ----
        float mt0 = -1e30f, mt1 = -1e30f;
#pragma unroll
        for (int nt = 0; nt < 8; nt++) {
#pragma unroll
            for (int i = 0; i < 4; i++) s[nt][i] *= scale;
            mt0 = fmaxf(mt0, fmaxf(s[nt][0], s[nt][1]));
            mt1 = fmaxf(mt1, fmaxf(s[nt][2], s[nt][3]));
        }
        mt0 = fmaxf(mt0, __shfl_xor_sync(0xffffffffu, mt0, 1));
        mt0 = fmaxf(mt0, __shfl_xor_sync(0xffffffffu, mt0, 2));
        mt1 = fmaxf(mt1, __shfl_xor_sync(0xffffffffu, mt1, 1));
        mt1 = fmaxf(mt1, __shfl_xor_sync(0xffffffffu, mt1, 2));

        float mn0 = fmaxf(m0, mt0), mn1 = fmaxf(m1, mt1);
        float al0 = __expf(m0 - mn0), al1 = __expf(m1 - mn1);
        float ls0 = 0.f, ls1 = 0.f;

#pragma unroll
        for (int nt = 0; nt < 8; nt++) {
            float p0 = __expf(s[nt][0] - mn0);
            float p1 = __expf(s[nt][1] - mn0);
            float p2 = __expf(s[nt][2] - mn1);
            float p3 = __expf(s[nt][3] - mn1);
            ls0 += p0 + p1;
            ls1 += p2 + p3;
            // permuted scatter into sP (4B stores; conflict-free per half-warp)
            sP[(wr + grp    ) * PP + nt * 8 + pp0] = f2tf32(p0);
            sP[(wr + grp    ) * PP + nt * 8 + pp1] = f2tf32(p1);
            sP[(wr + grp + 8) * PP + nt * 8 + pp0] = f2tf32(p2);
            sP[(wr + grp + 8) * PP + nt * 8 + pp1] = f2tf32(p3);
        }
        ls0 += __shfl_xor_sync(0xffffffffu, ls0, 1);
        ls0 += __shfl_xor_sync(0xffffffffu, ls0, 2);
        ls1 += __shfl_xor_sync(0xffffffffu, ls1, 1);
        ls1 += __shfl_xor_sync(0xffffffffu, ls1, 2);

        l0 = l0 * al0 + ls0;  m0 = mn0;
        l1 = l1 * al1 + ls1;  m1 = mn1;
#pragma unroll
        for (int nt = 0; nt < 12; nt++) {
            o[nt][0] *= al0; o[nt][1] *= al0;
            o[nt][2] *= al1; o[nt][3] *= al1;
        }
        __syncwarp();

        // ---- O += P V ; 64-bit A and B loads ----
#pragma unroll
        for (int ks = 0; ks < 8; ks++) {
            const int kk = ks * 8 + 2 * thr;
            uint2 pa0 = *(uint2*)&sP[(wr + grp    ) * PP + kk];  // (a0, a2)
            uint2 pa1 = *(uint2*)&sP[(wr + grp + 8) * PP + kk];  // (a1, a3)
#pragma unroll
            for (int nt = 0; nt < 12; nt++) {
                uint2 vb = *(uint2*)&sVT[(nt * 8 + grp) * VP + kk];
                mma_tf32(o[nt][0], o[nt][1], o[nt][2], o[nt][3],
                         pa0.x, pa1.x, pa0.y, pa1.y, vb.x, vb.y);
            }
        }
    }

    // epilogue: normalize + tf32-round (feeds cvt-free Wo GEMM)
    float inv0 = 1.f / l0, inv1 = 1.f / l1;
    size_t row0 = ((size_t)b * SEQL + q0 + wr + grp    ) * DIMS + h * HD;
    size_t row1 = ((size_t)b * SEQL + q0 + wr + grp + 8) * DIMS + h * HD;
#pragma unroll
    for (int nt = 0; nt < 12; nt++) {
        int c = nt * 8 + thr * 2;
        *(float2*)(O + row0 + c) = make_float2(
            __uint_as_float(f2tf32(o[nt][0] * inv0)),
            __uint_as_float(f2tf32(o[nt][1] * inv0)));
        *(float2*)(O + row1 + c) = make_float2(
            __uint_as_float(f2tf32(o[nt][2] * inv1)),
            __uint_as_float(f2tf32(o[nt][3] * inv1)));
    }
}

// ---------------------------------------------------------------------------
// Launch
// ---------------------------------------------------------------------------
extern "C" void kernel_launch(void* const* d_in, const int* in_sizes, int n_in,
                              void* d_out, int out_size)
{
    const float* Q_in = (const float*)d_in[0];
    const float* K_in = (const float*)d_in[1];
    const float* V_in = (const float*)d_in[2];
    const float* cq   = (const float*)d_in[3];
    const float* ck   = (const float*)d_in[4];
    const float* Wq   = (const float*)d_in[5];
    const float* Wk   = (const float*)d_in[6];
    const float* Wv   = (const float*)d_in[7];
    const float* Wo   = (const float*)d_in[8];
    float* out = (float*)d_out;

    float *q, *k, *v, *q2, *k2, *att, *wq, *wk, *wv, *wo;
    uint32_t* vt;
    cudaGetSymbolAddress((void**)&q,   g_q);
    cudaGetSymbolAddress((void**)&k,   g_k);
    cudaGetSymbolAddress((void**)&v,   g_v);
    cudaGetSymbolAddress((void**)&q2,  g_q2);
    cudaGetSymbolAddress((void**)&k2,  g_k2);
    cudaGetSymbolAddress((void**)&att, g_att);
    cudaGetSymbolAddress((void**)&vt,  g_vt);
    cudaGetSymbolAddress((void**)&wq,  g_wq);
    cudaGetSymbolAddress((void**)&wk,  g_wk);
    cudaGetSymbolAddress((void**)&wv,  g_wv);
    cudaGetSymbolAddress((void**)&wo,  g_wo);

    cudaFuncSetAttribute(gemm_qkv_kernel, cudaFuncAttributeMaxDynamicSharedMemorySize,
                         GEMM_SMEM_BYTES);
    cudaFuncSetAttribute(gemm_wo_kernel, cudaFuncAttributeMaxDynamicSharedMemorySize,
                         GEMM_SMEM_BYTES);
    cudaFuncSetAttribute(attn_mma_kernel, cudaFuncAttributeMaxDynamicSharedMemorySize,
                         ATTN_SMEM_BYTES);

    round_weights_kernel<<<dim3(DIMS * DIMS / 4 / 256, 4), 256>>>(
        Wq, Wk, Wv, Wo, wq, wk, wv, wo);

    gemm_qkv_kernel<<<dim3(NROWS / TM, DIMS / TN, 3), 256, GEMM_SMEM_BYTES>>>(
        Q_in, K_in, V_in, wq, wk, wv, q, k, v);

    pointwise_kernel<<<dim3(ROPE_BLOCKS, 3), 256>>>(q, q2, cq, k, k2, ck, v, vt);

    attn_mma_kernel<<<dim3(SEQL / BQ, HEADS, BATCH), 128, ATTN_SMEM_BYTES>>>(q2, k2, vt, att);

    gemm_wo_kernel<<<dim3(NROWS / TM, DIMS / TN), 256, GEMM_SMEM_BYTES>>>(att, wo, out);
}

// round 13
// speedup vs baseline: 1.1836x; 1.0390x over previous
#include <cuda_runtime.h>
#include <math.h>
#include <stdint.h>

#define DIMS   768
#define HEADS  8
#define HD     96
#define SEQL   2048
#define BATCH  2
#define NROWS  (BATCH*SEQL)   // 4096

// ---------------------------------------------------------------------------
// Scratch (static device globals)
// ---------------------------------------------------------------------------
__device__ float    g_q  [NROWS*DIMS];
__device__ float    g_k  [NROWS*DIMS];
__device__ float    g_v  [NROWS*DIMS];
__device__ float    g_q2 [NROWS*DIMS];            // rope(q), k-permuted layout
__device__ float    g_k2 [NROWS*DIMS];            // rope(k), k-permuted layout
__device__ float    g_att[NROWS*DIMS];
__device__ uint32_t g_vt [BATCH*HEADS*HD*SEQL];   // V^T, tf32 bits, token-permuted
__device__ float    g_wq [DIMS*DIMS];
__device__ float    g_wk [DIMS*DIMS];
__device__ float    g_wv [DIMS*DIMS];
__device__ float    g_wo [DIMS*DIMS];

// ---------------------------------------------------------------------------
// PTX helpers
// ---------------------------------------------------------------------------
__device__ __forceinline__ uint32_t smem_u32(const void* p) {
    uint32_t a;
    asm("{ .reg .u64 t; cvta.to.shared.u64 t, %1; cvt.u32.u64 %0, t; }" : "=r"(a) : "l"(p));
    return a;
}
__device__ __forceinline__ void cp_async16(uint32_t dst, const void* src) {
    asm volatile("cp.async.cg.shared.global [%0], [%1], 16;" :: "r"(dst), "l"(src));
}
__device__ __forceinline__ void cp_async_commit() { asm volatile("cp.async.commit_group;" ::: "memory"); }
template<int N>
__device__ __forceinline__ void cp_async_wait() { asm volatile("cp.async.wait_group %0;" :: "n"(N) : "memory"); }

__device__ __forceinline__ uint32_t f2tf32(float x) {
    uint32_t u;
    asm("cvt.rna.tf32.f32 %0, %1;" : "=r"(u) : "f"(x));
    return u;
}
__device__ __forceinline__ void mma_tf32(float& c0, float& c1, float& c2, float& c3,
                                         uint32_t a0, uint32_t a1, uint32_t a2, uint32_t a3,
                                         uint32_t b0, uint32_t b1) {
    asm volatile(
        "mma.sync.aligned.m16n8k8.row.col.f32.tf32.tf32.f32 "
        "{%0,%1,%2,%3}, {%4,%5,%6,%7}, {%8,%9}, {%0,%1,%2,%3};"
        : "+f"(c0), "+f"(c1), "+f"(c2), "+f"(c3)
        : "r"(a0), "r"(a1), "r"(a2), "r"(a3), "r"(b0), "r"(b1));
}

// k-group permutation: within each 8-element group, r -> 2*(r%4) + r/4.
__device__ __forceinline__ int perm8(int c) {
    return (c & ~7) | (((c & 3) << 1) | ((c >> 2) & 1));
}

// ---------------------------------------------------------------------------
// tf32 pre-rounding of the 4 weight matrices
// ---------------------------------------------------------------------------
__device__ __forceinline__ float4 round4(float4 x) {
    return make_float4(__uint_as_float(f2tf32(x.x)), __uint_as_float(f2tf32(x.y)),
                       __uint_as_float(f2tf32(x.z)), __uint_as_float(f2tf32(x.w)));
}
__global__ __launch_bounds__(256)
void round_weights_kernel(const float* __restrict__ a, const float* __restrict__ b,
                          const float* __restrict__ c, const float* __restrict__ d,
                          float* __restrict__ oa, float* __restrict__ ob,
                          float* __restrict__ oc, float* __restrict__ od)
{
    const float* src; float* dst;
    if      (blockIdx.y == 0) { src = a; dst = oa; }
    else if (blockIdx.y == 1) { src = b; dst = ob; }
    else if (blockIdx.y == 2) { src = c; dst = oc; }
    else                      { src = d; dst = od; }
    int i = blockIdx.x * 256 + threadIdx.x;
    ((float4*)dst)[i] = round4(((const float4*)src)[i]);
}

// ---------------------------------------------------------------------------
// NT GEMM via mma.sync tf32 (unchanged from R12).
// ---------------------------------------------------------------------------
#define TM   128
#define TN   128
#define KCH  32
#define PITCH 36
#define NSTAGE 3
#define STAGE_F (TM * PITCH)
#define GEMM_SMEM_BYTES (2 * NSTAGE * STAGE_F * 4)   // 110592 B

template<bool CVT_A>
__device__ __forceinline__
void gemm_body(const float* __restrict__ A, const float* __restrict__ B,
               float* __restrict__ C, int M, int N, int K, float* smem)
{
    float* sA = smem;
    float* sB = smem + NSTAGE * STAGE_F;

    const int tid  = threadIdx.x;
    const int wid  = tid >> 5;
    const int lane = tid & 31;
    const int grp  = lane >> 2;
    const int thr  = lane & 3;
    const int wm   = (wid & 3) * 32;
    const int wn   = (wid >> 2) * 64;
    const int rowBase = blockIdx.x * TM;
    const int colBase = blockIdx.y * TN;

    const uint32_t sA_u = smem_u32(sA);
    const uint32_t sB_u = smem_u32(sB);

    float acc[2][8][4];
#pragma unroll
    for (int mt = 0; mt < 2; mt++)
#pragma unroll
        for (int nt = 0; nt < 8; nt++)
#pragma unroll
            for (int i = 0; i < 4; i++) acc[mt][nt][i] = 0.f;

    const int nChunks = K / KCH;

#define PREFETCH(ch)                                                            \
    do {                                                                        \
        int _k0 = (ch) * KCH;                                                   \
        uint32_t _dA = sA_u + ((ch) % NSTAGE) * STAGE_F * 4;                    \
        uint32_t _dB = sB_u + ((ch) % NSTAGE) * STAGE_F * 4;                    \
        _Pragma("unroll")                                                       \
        for (int _it = 0; _it < 4; _it++) {                                     \
            int _idx = tid + _it * 256;                                         \
            int _r = _idx >> 3, _seg = _idx & 7;                                \
            cp_async16(_dA + (_r * PITCH + _seg * 4) * 4,                       \
                       A + (size_t)(rowBase + _r) * K + _k0 + _seg * 4);        \
            cp_async16(_dB + (_r * PITCH + _seg * 4) * 4,                       \
                       B + (size_t)(colBase + _r) * K + _k0 + _seg * 4);        \
        }                                                                       \
        cp_async_commit();                                                      \
    } while (0)

    PREFETCH(0);
    PREFETCH(1);

    for (int ch = 0; ch < nChunks; ch++) {
        if      (ch + 2 < nChunks) { PREFETCH(ch + 2); cp_async_wait<2>(); }
        else if (ch + 1 < nChunks) { cp_async_wait<1>(); }
        else                       { cp_async_wait<0>(); }
        __syncthreads();

        const float* cA = sA + (ch % NSTAGE) * STAGE_F;
        const float* cB = sB + (ch % NSTAGE) * STAGE_F;

#pragma unroll
        for (int ks = 0; ks < 4; ks++) {
            const int kk = ks * 8;
            uint32_t af[2][4];
#pragma unroll
            for (int mt = 0; mt < 2; mt++) {
                int rb = wm + mt * 16 + grp;
                float a0 = cA[(rb    ) * PITCH + kk + thr    ];
                float a1 = cA[(rb + 8) * PITCH + kk + thr    ];
                float a2 = cA[(rb    ) * PITCH + kk + thr + 4];
                float a3 = cA[(rb + 8) * PITCH + kk + thr + 4];
                if (CVT_A) {
                    af[mt][0] = f2tf32(a0); af[mt][1] = f2tf32(a1);
                    af[mt][2] = f2tf32(a2); af[mt][3] = f2tf32(a3);
                } else {
                    af[mt][0] = __float_as_uint(a0); af[mt][1] = __float_as_uint(a1);
                    af[mt][2] = __float_as_uint(a2); af[mt][3] = __float_as_uint(a3);
                }
            }
            uint32_t bf[8][2];
#pragma unroll
            for (int nt = 0; nt < 8; nt++) {
                int cb = wn + nt * 8 + grp;
                bf[nt][0] = __float_as_uint(cB[cb * PITCH + kk + thr    ]);
                bf[nt][1] = __float_as_uint(cB[cb * PITCH + kk + thr + 4]);
            }
#pragma unroll
            for (int mt = 0; mt < 2; mt++)
#pragma unroll
                for (int nt = 0; nt < 8; nt++)
                    mma_tf32(acc[mt][nt][0], acc[mt][nt][1],
                             acc[mt][nt][2], acc[mt][nt][3],
                             af[mt][0], af[mt][1], af[mt][2], af[mt][3],
                             bf[nt][0], bf[nt][1]);
        }
        __syncthreads();
    }
#undef PREFETCH

#pragma unroll
    for (int mt = 0; mt < 2; mt++) {
        int r0 = rowBase + wm + mt * 16 + grp;
#pragma unroll
        for (int nt = 0; nt < 8; nt++) {
            int c0 = colBase + wn + nt * 8 + thr * 2;
            float2* p0 = (float2*)(C + (size_t)r0 * N + c0);
            float2* p1 = (float2*)(C + (size_t)(r0 + 8) * N + c0);
            *p0 = make_float2(acc[mt][nt][0], acc[mt][nt][1]);
            *p1 = make_float2(acc[mt][nt][2], acc[mt][nt][3]);
        }
    }
}

__global__ __launch_bounds__(256)
void gemm_qkv_kernel(const float* __restrict__ Qin, const float* __restrict__ Kin,
                     const float* __restrict__ Vin, const float* __restrict__ Wq,
                     const float* __restrict__ Wk, const float* __restrict__ Wv,
                     float* __restrict__ q, float* __restrict__ k, float* __restrict__ v)
{
    extern __shared__ float smem[];
    const float *A, *B;
    float* C;
    if      (blockIdx.z == 0) { A = Qin; B = Wq; C = q; }
    else if (blockIdx.z == 1) { A = Kin; B = Wk; C = k; }
    else                      { A = Vin; B = Wv; C = v; }
    gemm_body<true>(A, B, C, NROWS, DIMS, DIMS, smem);
}

__global__ __launch_bounds__(256)
void gemm_wo_kernel(const float* __restrict__ A, const float* __restrict__ B,
                    float* __restrict__ C)
{
    extern __shared__ float smem[];
    gemm_body<false>(A, B, C, NROWS, DIMS, DIMS, smem);
}

// ---------------------------------------------------------------------------
// Fused pointwise: z=0 rope(q)->q2 (k-permuted), z=1 rope(k)->k2,
// z=2 transpose(v)->vt (token-permuted). All outputs tf32-rounded.
// ---------------------------------------------------------------------------
#define ROPE_BLOCKS ((NROWS * HEADS * 48) / 256)     // 6144
#define TRANS_BLOCKS ((DIMS / 32) * (NROWS / 32))    // 3072

__global__ __launch_bounds__(256)
void pointwise_kernel(const float* __restrict__ xq, float* __restrict__ oq,
                      const float* __restrict__ cq,
                      const float* __restrict__ xk, float* __restrict__ ok,
                      const float* __restrict__ ck,
                      const float* __restrict__ v, uint32_t* __restrict__ vt)
{
    __shared__ float t[32][33];
    const int z = blockIdx.y;

    if (z < 2) {
        const float* x      = z ? xk : xq;
        float* out          = z ? ok : oq;
        const float* coords = z ? ck : cq;

        int idx = blockIdx.x * 256 + threadIdx.x;
        int p  = idx % 48;
        int h  = (idx / 48) % HEADS;
        int bl = idx / (48 * HEADS);
        int axis = p >> 4;
        int j    = p & 15;

        float coord = coords[(size_t)bl * 3 + axis];
        float inv = exp2f(-(float)j * (0.0625f * 13.28771238f));  // log2(1e4)/16
        float ang = coord * inv;
        float s, c;
        sincosf(ang, &s, &c);

        size_t base = (size_t)bl * DIMS + h * HD;
        int c1 = axis * 32 + j;
        int c2 = c1 + 16;
        float x1 = x[base + c1];
        float x2 = x[base + c2];
        out[base + perm8(c1)] = __uint_as_float(f2tf32(x1 * c - x2 * s));
        out[base + perm8(c2)] = __uint_as_float(f2tf32(x1 * s + x2 * c));
    } else {
        if (blockIdx.x >= TRANS_BLOCKS) return;
        const int tx = threadIdx.x & 31;
        const int ty = threadIdx.x >> 5;
        const int c0 = (blockIdx.x % (DIMS / 32)) * 32;
        const int r0 = (blockIdx.x / (DIMS / 32)) * 32;

#pragma unroll
        for (int i = 0; i < 4; i++)
            t[ty + i * 8][tx] = v[(size_t)(r0 + ty + i * 8) * DIMS + c0 + tx];
        __syncthreads();

        int txp = perm8(tx);   // token-permuted position within 32-block
#pragma unroll
        for (int i = 0; i < 4; i++) {
            int c = c0 + ty + i * 8;
            int h = c / HD, d = c % HD;
            int b = r0 >> 11, tl = r0 & 2047;
            vt[((size_t)(b * HEADS + h) * HD + d) * SEQL + tl + txp] =
                f2tf32(t[tx][ty + i * 8]);
        }
    }
}

// ---------------------------------------------------------------------------
// Flash attention, mma.sync tf32. BQ=64, BK=64, 128 threads (4 warps).
// - sK rows stored key-permuted  -> S C-fragment layout == PV A-fragment
//   layout (P never leaves registers; no sP buffer, no extra sync).
// - Q hoisted to registers; sQ buffer eliminated.
// - 2-stage double-buffered K/V cp.async pipeline: [K0|K1|V0|V1] = 108.5KB,
//   still 2 CTAs/SM.
// ---------------------------------------------------------------------------
#define BQ 64
#define BK 64
#define QP 104
#define VP 72
#define KBUF (BK*QP)                     // 6656 words
#define VBUF (HD*VP)                     // 6912 words
#define ATTN_SMEM_U32 (2*KBUF + 2*VBUF)  // 27136
#define ATTN_SMEM_BYTES (ATTN_SMEM_U32 * 4)  // 108544

__global__ __launch_bounds__(128)
void attn_mma_kernel(const float* __restrict__ q, const float* __restrict__ k,
                     const uint32_t* __restrict__ vt, float* __restrict__ O)
{
    extern __shared__ uint32_t smu[];
    uint32_t* sK0  = smu;
    uint32_t* sK1  = smu + KBUF;
    uint32_t* sV0  = smu + 2 * KBUF;
    uint32_t* sV1  = smu + 2 * KBUF + VBUF;

    const int tid  = threadIdx.x;
    const int lane = tid & 31;
    const int grp  = lane >> 2;
    const int thr  = lane & 3;
    const int wr   = (tid >> 5) * 16;
    const int q0   = blockIdx.x * BQ;
    const int h    = blockIdx.y;
    const int b    = blockIdx.z;

    const uint32_t sK0_u = smem_u32(sK0);
    const uint32_t sK1_u = smem_u32(sK1);
    const uint32_t sV0_u = smem_u32(sV0);
    const uint32_t sV1_u = smem_u32(sV1);

    const float scale = rsqrtf((float)HD);

    const float*    Qb = q  + ((size_t)b * SEQL + q0) * DIMS + h * HD;
    const float*    Kb = k  + (size_t)b * SEQL * DIMS + h * HD;
    const uint32_t* Vb = vt + (size_t)(b * HEADS + h) * HD * SEQL;

    // ---- load Q into K0 region, hoist fragments to registers ----
#pragma unroll
    for (int i = 0; i < 12; i++) {
        int idx = tid + i * 128;
        int r = idx / 24, c4 = idx % 24;
        cp_async16(sK0_u + (r * QP + c4 * 4) * 4, Qb + (size_t)r * DIMS + c4 * 4);
    }
    cp_async_commit();
    cp_async_wait<0>();
    __syncthreads();

    uint2 qf0[12], qf1[12];
#pragma unroll
    for (int ks = 0; ks < 12; ks++) {
        qf0[ks] = *(uint2*)&sK0[(wr + grp    ) * QP + ks * 8 + 2 * thr];  // (a0, a2)
        qf1[ks] = *(uint2*)&sK0[(wr + grp + 8) * QP + ks * 8 + 2 * thr];  // (a1, a3)
    }
    __syncthreads();   // hoist reads complete before K0 is overwritten

    // K rows stored permuted: dst row = perm8(src key) -> S col i = key sigma(i)
#define PREF_KV(kb)                                                              \
    do {                                                                         \
        int _k0 = (kb) * BK;                                                     \
        uint32_t _dK = ((kb) & 1) ? sK1_u : sK0_u;                               \
        uint32_t _dV = ((kb) & 1) ? sV1_u : sV0_u;                               \
        _Pragma("unroll")                                                        \
        for (int _i = 0; _i < 12; _i++) {                                        \
            int _idx = tid + _i * 128;                                           \
            int _r = _idx / 24, _c4 = _idx % 24;                                 \
            cp_async16(_dK + (perm8(_r) * QP + _c4 * 4) * 4,                     \
                       Kb + (size_t)(_k0 + _r) * DIMS + _c4 * 4);                \
        }                                                                        \
        _Pragma("unroll")                                                        \
        for (int _i = 0; _i < 12; _i++) {                                        \
            int _idx = tid + _i * 128;                                           \
            int _d = _idx / 16, _c4 = _idx % 16;                                 \
            cp_async16(_dV + (_d * VP + _c4 * 4) * 4,                            \
                       Vb + (size_t)_d * SEQL + _k0 + _c4 * 4);                  \
        }                                                                        \
        cp_async_commit();                                                       \
    } while (0)

    PREF_KV(0);
    PREF_KV(1);

    float m0 = -1e30f, m1 = -1e30f, l0 = 0.f, l1 = 0.f;
    float o[12][4];
#pragma unroll
    for (int nt = 0; nt < 12; nt++)
#pragma unroll
        for (int i = 0; i < 4; i++) o[nt][i] = 0.f;

    const int NT = SEQL / BK;   // 32
    for (int kb = 0; kb < NT; kb++) {
        if (kb + 1 < NT) cp_async_wait<1>();
        else             cp_async_wait<0>();
        __syncthreads();

        const uint32_t* cK = (kb & 1) ? sK1 : sK0;
        const uint32_t* cV = (kb & 1) ? sV1 : sV0;

        // ---- S = Q K^T (warp: 16 q-rows x 64 keys); 64-bit B loads ----
        float s[8][4];
#pragma unroll
        for (int nt = 0; nt < 8; nt++)
#pragma unroll
            for (int i = 0; i < 4; i++) s[nt][i] = 0.f;

#pragma unroll
        for (int ks = 0; ks < 12; ks++) {
            const int kk = ks * 8 + 2 * thr;
            const uint2 a0 = qf0[ks], a1 = qf1[ks];
#pragma unroll
            for (int nt = 0; nt < 8; nt++) {
                uint2 bb = *(uint2*)&cK[(nt * 8 + grp) * QP + kk];
                mma_tf32(s[nt][0], s[nt][1], s[nt][2], s[nt][3],
                         a0.x, a1.x, a0.y, a1.y, bb.x, bb.y);
            }
        }

        // ---- online softmax (rows grp, grp+8); P stays in s[][] ----
        float mt0 = -1e30f, mt1 = -1e30f;
#pragma unroll
        for (int nt = 0; nt < 8; nt++) {
#pragma unroll
            for (int i = 0; i < 4; i++) s[nt][i] *= scale;
            mt0 = fmaxf(mt0, fmaxf(s[nt][0], s[nt][1]));
            mt1 = fmaxf(mt1, fmaxf(s[nt][2], s[nt][3]));
        }
        mt0 = fmaxf(mt0, __shfl_xor_sync(0xffffffffu, mt0, 1));
        mt0 = fmaxf(mt0, __shfl_xor_sync(0xffffffffu, mt0, 2));
        mt1 = fmaxf(mt1, __shfl_xor_sync(0xffffffffu, mt1, 1));
        mt1 = fmaxf(mt1, __shfl_xor_sync(0xffffffffu, mt1, 2));

        float mn0 = fmaxf(m0, mt0), mn1 = fmaxf(m1, mt1);
        float al0 = __expf(m0 - mn0), al1 = __expf(m1 - mn1);
        float ls0 = 0.f, ls1 = 0.f;

#pragma unroll
        for (int nt = 0; nt < 8; nt++) {
            s[nt][0] = __expf(s[nt][0] - mn0);
            s[nt][1] = __expf(s[nt][1] - mn0);
            s[nt][2] = __expf(s[nt][2] - mn1);
            s[nt][3] = __expf(s[nt][3] - mn1);
            ls0 += s[nt][0] + s[nt][1];
            ls1 += s[nt][2] + s[nt][3];
        }
        ls0 += __shfl_xor_sync(0xffffffffu, ls0, 1);
        ls0 += __shfl_xor_sync(0xffffffffu, ls0, 2);
        ls1 += __shfl_xor_sync(0xffffffffu, ls1, 1);
        ls1 += __shfl_xor_sync(0xffffffffu, ls1, 2);

        l0 = l0 * al0 + ls0;  m0 = mn0;
        l1 = l1 * al1 + ls1;  m1 = mn1;
#pragma unroll
        for (int nt = 0; nt < 12; nt++) {
            o[nt][0] *= al0; o[nt][1] *= al0;
            o[nt][2] *= al1; o[nt][3] *= al1;
        }

        // ---- O += P V ; A direct from S fragments (layout-matched) ----
#pragma unroll
        for (int ks = 0; ks < 8; ks++) {
            const int kk = ks * 8 + 2 * thr;
            uint32_t pa0 = f2tf32(s[ks][0]);   // (grp,   k thr)
            uint32_t pa1 = f2tf32(s[ks][2]);   // (grp+8, k thr)
            uint32_t pa2 = f2tf32(s[ks][1]);   // (grp,   k thr+4)
            uint32_t pa3 = f2tf32(s[ks][3]);   // (grp+8, k thr+4)
#pragma unroll
            for (int nt = 0; nt < 12; nt++) {
                uint2 vb = *(uint2*)&cV[(nt * 8 + grp) * VP + kk];
                mma_tf32(o[nt][0], o[nt][1], o[nt][2], o[nt][3],
                         pa0, pa1, pa2, pa3, vb.x, vb.y);
            }
        }

        __syncthreads();   // all warps done with this buffer before refill
        if (kb + 2 < NT) PREF_KV(kb + 2);
    }
#undef PREF_KV

    // epilogue: normalize + tf32-round (feeds cvt-free Wo GEMM)
    float inv0 = 1.f / l0, inv1 = 1.f / l1;
    size_t row0 = ((size_t)b * SEQL + q0 + wr + grp    ) * DIMS + h * HD;
    size_t row1 = ((size_t)b * SEQL + q0 + wr + grp + 8) * DIMS + h * HD;
#pragma unroll
    for (int nt = 0; nt < 12; nt++) {
        int c = nt * 8 + thr * 2;
        *(float2*)(O + row0 + c) = make_float2(
            __uint_as_float(f2tf32(o[nt][0] * inv0)),
            __uint_as_float(f2tf32(o[nt][1] * inv0)));
        *(float2*)(O + row1 + c) = make_float2(
            __uint_as_float(f2tf32(o[nt][2] * inv1)),
            __uint_as_float(f2tf32(o[nt][3] * inv1)));
    }
}

// ---------------------------------------------------------------------------
// Launch
// ---------------------------------------------------------------------------
extern "C" void kernel_launch(void* const* d_in, const int* in_sizes, int n_in,
                              void* d_out, int out_size)
{
    const float* Q_in = (const float*)d_in[0];
    const float* K_in = (const float*)d_in[1];
    const float* V_in = (const float*)d_in[2];
    const float* cq   = (const float*)d_in[3];
    const float* ck   = (const float*)d_in[4];
    const float* Wq   = (const float*)d_in[5];
    const float* Wk   = (const float*)d_in[6];
    const float* Wv   = (const float*)d_in[7];
    const float* Wo   = (const float*)d_in[8];
    float* out = (float*)d_out;

    float *q, *k, *v, *q2, *k2, *att, *wq, *wk, *wv, *wo;
    uint32_t* vt;
    cudaGetSymbolAddress((void**)&q,   g_q);
    cudaGetSymbolAddress((void**)&k,   g_k);
    cudaGetSymbolAddress((void**)&v,   g_v);
    cudaGetSymbolAddress((void**)&q2,  g_q2);
    cudaGetSymbolAddress((void**)&k2,  g_k2);
    cudaGetSymbolAddress((void**)&att, g_att);
    cudaGetSymbolAddress((void**)&vt,  g_vt);
    cudaGetSymbolAddress((void**)&wq,  g_wq);
    cudaGetSymbolAddress((void**)&wk,  g_wk);
    cudaGetSymbolAddress((void**)&wv,  g_wv);
    cudaGetSymbolAddress((void**)&wo,  g_wo);

    cudaFuncSetAttribute(gemm_qkv_kernel, cudaFuncAttributeMaxDynamicSharedMemorySize,
                         GEMM_SMEM_BYTES);
    cudaFuncSetAttribute(gemm_wo_kernel, cudaFuncAttributeMaxDynamicSharedMemorySize,
                         GEMM_SMEM_BYTES);
    cudaFuncSetAttribute(attn_mma_kernel, cudaFuncAttributeMaxDynamicSharedMemorySize,
                         ATTN_SMEM_BYTES);

    round_weights_kernel<<<dim3(DIMS * DIMS / 4 / 256, 4), 256>>>(
        Wq, Wk, Wv, Wo, wq, wk, wv, wo);

    gemm_qkv_kernel<<<dim3(NROWS / TM, DIMS / TN, 3), 256, GEMM_SMEM_BYTES>>>(
        Q_in, K_in, V_in, wq, wk, wv, q, k, v);

    pointwise_kernel<<<dim3(ROPE_BLOCKS, 3), 256>>>(q, q2, cq, k, k2, ck, v, vt);

    attn_mma_kernel<<<dim3(SEQL / BQ, HEADS, BATCH), 128, ATTN_SMEM_BYTES>>>(q2, k2, vt, att);

    gemm_wo_kernel<<<dim3(NROWS / TM, DIMS / TN), 256, GEMM_SMEM_BYTES>>>(att, wo, out);
}

// round 15
// speedup vs baseline: 1.2072x; 1.0200x over previous
#include <cuda_runtime.h>
#include <math.h>
#include <stdint.h>

#define DIMS   768
#define HEADS  8
#define HD     96
#define SEQL   2048
#define BATCH  2
#define NROWS  (BATCH*SEQL)   // 4096

// ---------------------------------------------------------------------------
// Scratch (static device globals)
// ---------------------------------------------------------------------------
__device__ float    g_q  [NROWS*DIMS];
__device__ float    g_k  [NROWS*DIMS];
__device__ float    g_v  [NROWS*DIMS];
__device__ float    g_q2 [NROWS*DIMS];            // rope(q), k-permuted layout
__device__ float    g_k2 [NROWS*DIMS];            // rope(k), k-permuted layout
__device__ float    g_att[NROWS*DIMS];
__device__ uint32_t g_vt [BATCH*HEADS*HD*SEQL];   // V^T, tf32 bits, token-permuted
__device__ float    g_wq [DIMS*DIMS];             // tf32-rounded, k-permuted
__device__ float    g_wk [DIMS*DIMS];
__device__ float    g_wv [DIMS*DIMS];
__device__ float    g_wo [DIMS*DIMS];

// ---------------------------------------------------------------------------
// PTX helpers
// ---------------------------------------------------------------------------
__device__ __forceinline__ uint32_t smem_u32(const void* p) {
    uint32_t a;
    asm("{ .reg .u64 t; cvta.to.shared.u64 t, %1; cvt.u32.u64 %0, t; }" : "=r"(a) : "l"(p));
    return a;
}
__device__ __forceinline__ void cp_async16(uint32_t dst, const void* src) {
    asm volatile("cp.async.cg.shared.global [%0], [%1], 16;" :: "r"(dst), "l"(src));
}
__device__ __forceinline__ void cp_async_commit() { asm volatile("cp.async.commit_group;" ::: "memory"); }
template<int N>
__device__ __forceinline__ void cp_async_wait() { asm volatile("cp.async.wait_group %0;" :: "n"(N) : "memory"); }

__device__ __forceinline__ uint32_t f2tf32(float x) {
    uint32_t u;
    asm("cvt.rna.tf32.f32 %0, %1;" : "=r"(u) : "f"(x));
    return u;
}
__device__ __forceinline__ void mma_tf32(float& c0, float& c1, float& c2, float& c3,
                                         uint32_t a0, uint32_t a1, uint32_t a2, uint32_t a3,
                                         uint32_t b0, uint32_t b1) {
    asm volatile(
        "mma.sync.aligned.m16n8k8.row.col.f32.tf32.tf32.f32 "
        "{%0,%1,%2,%3}, {%4,%5,%6,%7}, {%8,%9}, {%0,%1,%2,%3};"
        : "+f"(c0), "+f"(c1), "+f"(c2), "+f"(c3)
        : "r"(a0), "r"(a1), "r"(a2), "r"(a3), "r"(b0), "r"(b1));
}

// k-group permutation: within each 8-element group, r -> 2*(r%4) + r/4.
__device__ __forceinline__ int perm8(int c) {
    return (c & ~7) | (((c & 3) << 1) | ((c >> 2) & 1));
}

// ---------------------------------------------------------------------------
// tf32 pre-rounding + k-permutation of the 4 weight matrices.
// Permuted layout makes GEMM B-fragment pairs (thr, thr+4) adjacent -> LDS.64.
// ---------------------------------------------------------------------------
__global__ __launch_bounds__(256)
void round_weights_kernel(const float* __restrict__ a, const float* __restrict__ b,
                          const float* __restrict__ c, const float* __restrict__ d,
                          float* __restrict__ oa, float* __restrict__ ob,
                          float* __restrict__ oc, float* __restrict__ od)
{
    const float* src; float* dst;
    if      (blockIdx.y == 0) { src = a; dst = oa; }
    else if (blockIdx.y == 1) { src = b; dst = ob; }
    else if (blockIdx.y == 2) { src = c; dst = oc; }
    else                      { src = d; dst = od; }
    int base = (blockIdx.x * 256 + threadIdx.x) * 4;
    float4 x = *(const float4*)(src + base);
    dst[perm8(base + 0)] = __uint_as_float(f2tf32(x.x));
    dst[perm8(base + 1)] = __uint_as_float(f2tf32(x.y));
    dst[perm8(base + 2)] = __uint_as_float(f2tf32(x.z));
    dst[perm8(base + 3)] = __uint_as_float(f2tf32(x.w));
}

// ---------------------------------------------------------------------------
// NT GEMM via mma.sync tf32. B (weights) pre-rounded AND k-permuted ->
// B fragments are single LDS.64 (conflict-free with BPITCH=40).
// A unpermuted (scalar frag loads, cvt iff CVT_A). 2-stage cp.async pipeline.
// ---------------------------------------------------------------------------
#define TM   128
#define TN   128
#define KCH  32
#define APITCH 36
#define BPITCH 40
#define ASTAGE (TM * APITCH)    // 4608 floats
#define BSTAGE (TM * BPITCH)    // 5120 floats
#define GEMM_SMEM_BYTES ((2 * ASTAGE + 2 * BSTAGE) * 4)   // 77824 B

template<bool CVT_A>
__device__ __forceinline__
void gemm_body(const float* __restrict__ A, const float* __restrict__ B,
               float* __restrict__ C, int M, int N, int K, float* smem)
{
    float* sA = smem;                      // 2 stages
    float* sB = smem + 2 * ASTAGE;         // 2 stages

    const int tid  = threadIdx.x;
    const int wid  = tid >> 5;
    const int lane = tid & 31;
    const int grp  = lane >> 2;
    const int thr  = lane & 3;
    const int wm   = (wid & 3) * 32;
    const int wn   = (wid >> 2) * 64;
    const int rowBase = blockIdx.x * TM;
    const int colBase = blockIdx.y * TN;

    const uint32_t sA_u = smem_u32(sA);
    const uint32_t sB_u = smem_u32(sB);

    float acc[2][8][4];
#pragma unroll
    for (int mt = 0; mt < 2; mt++)
#pragma unroll
        for (int nt = 0; nt < 8; nt++)
#pragma unroll
            for (int i = 0; i < 4; i++) acc[mt][nt][i] = 0.f;

    const int nChunks = K / KCH;   // 24

#define PREFETCH(ch)                                                            \
    do {                                                                        \
        int _k0 = (ch) * KCH;                                                   \
        uint32_t _dA = sA_u + ((ch) & 1) * ASTAGE * 4;                          \
        uint32_t _dB = sB_u + ((ch) & 1) * BSTAGE * 4;                          \
        _Pragma("unroll")                                                       \
        for (int _it = 0; _it < 4; _it++) {                                     \
            int _idx = tid + _it * 256;                                         \
            int _r = _idx >> 3, _seg = _idx & 7;                                \
            cp_async16(_dA + (_r * APITCH + _seg * 4) * 4,                      \
                       A + (size_t)(rowBase + _r) * K + _k0 + _seg * 4);        \
            cp_async16(_dB + (_r * BPITCH + _seg * 4) * 4,                      \
                       B + (size_t)(colBase + _r) * K + _k0 + _seg * 4);        \
        }                                                                       \
        cp_async_commit();                                                      \
    } while (0)

    PREFETCH(0);
    PREFETCH(1);

    for (int ch = 0; ch < nChunks; ch++) {
        if (ch + 1 < nChunks) cp_async_wait<1>();
        else                  cp_async_wait<0>();
        __syncthreads();

        const float* cA = sA + (ch & 1) * ASTAGE;
        const float* cB = sB + (ch & 1) * BSTAGE;

#pragma unroll
        for (int ks = 0; ks < 4; ks++) {
            const int kk = ks * 8;
            uint32_t af[2][4];
#pragma unroll
            for (int mt = 0; mt < 2; mt++) {
                int rb = wm + mt * 16 + grp;
                float a0 = cA[(rb    ) * APITCH + kk + thr    ];
                float a1 = cA[(rb + 8) * APITCH + kk + thr    ];
                float a2 = cA[(rb    ) * APITCH + kk + thr + 4];
                float a3 = cA[(rb + 8) * APITCH + kk + thr + 4];
                if (CVT_A) {
                    af[mt][0] = f2tf32(a0); af[mt][1] = f2tf32(a1);
                    af[mt][2] = f2tf32(a2); af[mt][3] = f2tf32(a3);
                } else {
                    af[mt][0] = __float_as_uint(a0); af[mt][1] = __float_as_uint(a1);
                    af[mt][2] = __float_as_uint(a2); af[mt][3] = __float_as_uint(a3);
                }
            }
            uint2 bf[8];
#pragma unroll
            for (int nt = 0; nt < 8; nt++) {
                int cb = wn + nt * 8 + grp;
                bf[nt] = *(const uint2*)&cB[cb * BPITCH + kk + 2 * thr];
            }
#pragma unroll
            for (int mt = 0; mt < 2; mt++)
#pragma unroll
                for (int nt = 0; nt < 8; nt++)
                    mma_tf32(acc[mt][nt][0], acc[mt][nt][1],
                             acc[mt][nt][2], acc[mt][nt][3],
                             af[mt][0], af[mt][1], af[mt][2], af[mt][3],
                             bf[nt].x, bf[nt].y);
        }
        __syncthreads();
        if (ch + 2 < nChunks) PREFETCH(ch + 2);
    }
#undef PREFETCH

#pragma unroll
    for (int mt = 0; mt < 2; mt++) {
        int r0 = rowBase + wm + mt * 16 + grp;
#pragma unroll
        for (int nt = 0; nt < 8; nt++) {
            int c0 = colBase + wn + nt * 8 + thr * 2;
            float2* p0 = (float2*)(C + (size_t)r0 * N + c0);
            float2* p1 = (float2*)(C + (size_t)(r0 + 8) * N + c0);
            *p0 = make_float2(acc[mt][nt][0], acc[mt][nt][1]);
            *p1 = make_float2(acc[mt][nt][2], acc[mt][nt][3]);
        }
    }
}

__global__ __launch_bounds__(256)
void gemm_qkv_kernel(const float* __restrict__ Qin, const float* __restrict__ Kin,
                     const float* __restrict__ Vin, const float* __restrict__ Wq,
                     const float* __restrict__ Wk, const float* __restrict__ Wv,
                     float* __restrict__ q, float* __restrict__ k, float* __restrict__ v)
{
    extern __shared__ float smem[];
    const float *A, *B;
    float* C;
    if      (blockIdx.z == 0) { A = Qin; B = Wq; C = q; }
    else if (blockIdx.z == 1) { A = Kin; B = Wk; C = k; }
    else                      { A = Vin; B = Wv; C = v; }
    gemm_body<true>(A, B, C, NROWS, DIMS, DIMS, smem);
}

__global__ __launch_bounds__(256)
void gemm_wo_kernel(const float* __restrict__ A, const float* __restrict__ B,
                    float* __restrict__ C)
{
    extern __shared__ float smem[];
    gemm_body<false>(A, B, C, NROWS, DIMS, DIMS, smem);
}

// ---------------------------------------------------------------------------
// Fused pointwise: z=0 rope(q)->q2 (k-permuted), z=1 rope(k)->k2,
// z=2 transpose(v)->vt (token-permuted). All outputs tf32-rounded.
// ---------------------------------------------------------------------------
#define ROPE_BLOCKS ((NROWS * HEADS * 48) / 256)     // 6144
#define TRANS_BLOCKS ((DIMS / 32) * (NROWS / 32))    // 3072

__global__ __launch_bounds__(256)
void pointwise_kernel(const float* __restrict__ xq, float* __restrict__ oq,
                      const float* __restrict__ cq,
                      const float* __restrict__ xk, float* __restrict__ ok,
                      const float* __restrict__ ck,
                      const float* __restrict__ v, uint32_t* __restrict__ vt)
{
    __shared__ float t[32][33];
    const int z = blockIdx.y;

    if (z < 2) {
        const float* x      = z ? xk : xq;
        float* out          = z ? ok : oq;
        const float* coords = z ? ck : cq;

        int idx = blockIdx.x * 256 + threadIdx.x;
        int p  = idx % 48;
        int h  = (idx / 48) % HEADS;
        int bl = idx / (48 * HEADS);
        int axis = p >> 4;
        int j    = p & 15;

        float coord = coords[(size_t)bl * 3 + axis];
        float inv = exp2f(-(float)j * (0.0625f * 13.28771238f));  // log2(1e4)/16
        float ang = coord * inv;
        float s, c;
        sincosf(ang, &s, &c);

        size_t base = (size_t)bl * DIMS + h * HD;
        int c1 = axis * 32 + j;
        int c2 = c1 + 16;
        float x1 = x[base + c1];
        float x2 = x[base + c2];
        out[base + perm8(c1)] = __uint_as_float(f2tf32(x1 * c - x2 * s));
        out[base + perm8(c2)] = __uint_as_float(f2tf32(x1 * s + x2 * c));
    } else {
        if (blockIdx.x >= TRANS_BLOCKS) return;
        const int tx = threadIdx.x & 31;
        const int ty = threadIdx.x >> 5;
        const int c0 = (blockIdx.x % (DIMS / 32)) * 32;
        const int r0 = (blockIdx.x / (DIMS / 32)) * 32;

#pragma unroll
        for (int i = 0; i < 4; i++)
            t[ty + i * 8][tx] = v[(size_t)(r0 + ty + i * 8) * DIMS + c0 + tx];
        __syncthreads();

        int txp = perm8(tx);   // token-permuted position within 32-block
#pragma unroll
        for (int i = 0; i < 4; i++) {
            int c = c0 + ty + i * 8;
            int h = c / HD, d = c % HD;
            int b = r0 >> 11, tl = r0 & 2047;
            vt[((size_t)(b * HEADS + h) * HD + d) * SEQL + tl + txp] =
                f2tf32(t[tx][ty + i * 8]);
        }
    }
}

// ---------------------------------------------------------------------------
// Flash attention, mma.sync tf32 (unchanged from R13 — best known).
// ---------------------------------------------------------------------------
#define BQ 64
#define BK 64
#define QP 104
#define VP 72
#define KBUF (BK*QP)                     // 6656 words
#define VBUF (HD*VP)                     // 6912 words
#define ATTN_SMEM_U32 (2*KBUF + 2*VBUF)  // 27136
#define ATTN_SMEM_BYTES (ATTN_SMEM_U32 * 4)  // 108544

__global__ __launch_bounds__(128)
void attn_mma_kernel(const float* __restrict__ q, const float* __restrict__ k,
                     const uint32_t* __restrict__ vt, float* __restrict__ O)
{
    extern __shared__ uint32_t smu[];
    uint32_t* sK0  = smu;
    uint32_t* sK1  = smu + KBUF;
    uint32_t* sV0  = smu + 2 * KBUF;
    uint32_t* sV1  = smu + 2 * KBUF + VBUF;

    const int tid  = threadIdx.x;
    const int lane = tid & 31;
    const int grp  = lane >> 2;
    const int thr  = lane & 3;
    const int wr   = (tid >> 5) * 16;
    const int q0   = blockIdx.x * BQ;
    const int h    = blockIdx.y;
    const int b    = blockIdx.z;

    const uint32_t sK0_u = smem_u32(sK0);
    const uint32_t sK1_u = smem_u32(sK1);
    const uint32_t sV0_u = smem_u32(sV0);
    const uint32_t sV1_u = smem_u32(sV1);

    const float scale = rsqrtf((float)HD);

    const float*    Qb = q  + ((size_t)b * SEQL + q0) * DIMS + h * HD;
    const float*    Kb = k  + (size_t)b * SEQL * DIMS + h * HD;
    const uint32_t* Vb = vt + (size_t)(b * HEADS + h) * HD * SEQL;

    // ---- load Q into K0 region, hoist fragments to registers ----
#pragma unroll
    for (int i = 0; i < 12; i++) {
        int idx = tid + i * 128;
        int r = idx / 24, c4 = idx % 24;
        cp_async16(sK0_u + (r * QP + c4 * 4) * 4, Qb + (size_t)r * DIMS + c4 * 4);
    }
    cp_async_commit();
    cp_async_wait<0>();
    __syncthreads();

    uint2 qf0[12], qf1[12];
#pragma unroll
    for (int ks = 0; ks < 12; ks++) {
        qf0[ks] = *(uint2*)&sK0[(wr + grp    ) * QP + ks * 8 + 2 * thr];  // (a0, a2)
        qf1[ks] = *(uint2*)&sK0[(wr + grp + 8) * QP + ks * 8 + 2 * thr];  // (a1, a3)
    }
    __syncthreads();   // hoist reads complete before K0 is overwritten

#define PREF_KV(kb)                                                              \
    do {                                                                         \
        int _k0 = (kb) * BK;                                                     \
        uint32_t _dK = ((kb) & 1) ? sK1_u : sK0_u;                               \
        uint32_t _dV = ((kb) & 1) ? sV1_u : sV0_u;                               \
        _Pragma("unroll")                                                        \
        for (int _i = 0; _i < 12; _i++) {                                        \
            int _idx = tid + _i * 128;                                           \
            int _r = _idx / 24, _c4 = _idx % 24;                                 \
            cp_async16(_dK + (perm8(_r) * QP + _c4 * 4) * 4,                     \
                       Kb + (size_t)(_k0 + _r) * DIMS + _c4 * 4);                \
        }                                                                        \
        _Pragma("unroll")                                                        \
        for (int _i = 0; _i < 12; _i++) {                                        \
            int _idx = tid + _i * 128;                                           \
            int _d = _idx / 16, _c4 = _idx % 16;                                 \
            cp_async16(_dV + (_d * VP + _c4 * 4) * 4,                            \
                       Vb + (size_t)_d * SEQL + _k0 + _c4 * 4);                  \
        }                                                                        \
        cp_async_commit();                                                       \
    } while (0)

    PREF_KV(0);
    PREF_KV(1);

    float m0 = -1e30f, m1 = -1e30f, l0 = 0.f, l1 = 0.f;
    float o[12][4];
#pragma unroll
    for (int nt = 0; nt < 12; nt++)
#pragma unroll
        for (int i = 0; i < 4; i++) o[nt][i] = 0.f;

    const int NT = SEQL / BK;   // 32
    for (int kb = 0; kb < NT; kb++) {
        if (kb + 1 < NT) cp_async_wait<1>();
        else             cp_async_wait<0>();
        __syncthreads();

        const uint32_t* cK = (kb & 1) ? sK1 : sK0;
        const uint32_t* cV = (kb & 1) ? sV1 : sV0;

        // ---- S = Q K^T ----
        float s[8][4];
#pragma unroll
        for (int nt = 0; nt < 8; nt++)
#pragma unroll
            for (int i = 0; i < 4; i++) s[nt][i] = 0.f;

#pragma unroll
        for (int ks = 0; ks < 12; ks++) {
            const int kk = ks * 8 + 2 * thr;
            const uint2 a0 = qf0[ks], a1 = qf1[ks];
#pragma unroll
            for (int nt = 0; nt < 8; nt++) {
                uint2 bb = *(uint2*)&cK[(nt * 8 + grp) * QP + kk];
                mma_tf32(s[nt][0], s[nt][1], s[nt][2], s[nt][3],
                         a0.x, a1.x, a0.y, a1.y, bb.x, bb.y);
            }
        }

        // ---- online softmax; P stays in registers ----
        float mt0 = -1e30f, mt1 = -1e30f;
#pragma unroll
        for (int nt = 0; nt < 8; nt++) {
#pragma unroll
            for (int i = 0; i < 4; i++) s[nt][i] *= scale;
            mt0 = fmaxf(mt0, fmaxf(s[nt][0], s[nt][1]));
            mt1 = fmaxf(mt1, fmaxf(s[nt][2], s[nt][3]));
        }
        mt0 = fmaxf(mt0, __shfl_xor_sync(0xffffffffu, mt0, 1));
        mt0 = fmaxf(mt0, __shfl_xor_sync(0xffffffffu, mt0, 2));
        mt1 = fmaxf(mt1, __shfl_xor_sync(0xffffffffu, mt1, 1));
        mt1 = fmaxf(mt1, __shfl_xor_sync(0xffffffffu, mt1, 2));

        float mn0 = fmaxf(m0, mt0), mn1 = fmaxf(m1, mt1);
        float al0 = __expf(m0 - mn0), al1 = __expf(m1 - mn1);
        float ls0 = 0.f, ls1 = 0.f;

#pragma unroll
        for (int nt = 0; nt < 8; nt++) {
            s[nt][0] = __expf(s[nt][0] - mn0);
            s[nt][1] = __expf(s[nt][1] - mn0);
            s[nt][2] = __expf(s[nt][2] - mn1);
            s[nt][3] = __expf(s[nt][3] - mn1);
            ls0 += s[nt][0] + s[nt][1];
            ls1 += s[nt][2] + s[nt][3];
        }
        ls0 += __shfl_xor_sync(0xffffffffu, ls0, 1);
        ls0 += __shfl_xor_sync(0xffffffffu, ls0, 2);
        ls1 += __shfl_xor_sync(0xffffffffu, ls1, 1);
        ls1 += __shfl_xor_sync(0xffffffffu, ls1, 2);

        l0 = l0 * al0 + ls0;  m0 = mn0;
        l1 = l1 * al1 + ls1;  m1 = mn1;
#pragma unroll
        for (int nt = 0; nt < 12; nt++) {
            o[nt][0] *= al0; o[nt][1] *= al0;
            o[nt][2] *= al1; o[nt][3] *= al1;
        }

        // ---- O += P V ; A direct from S fragments (layout-matched) ----
#pragma unroll
        for (int ks = 0; ks < 8; ks++) {
            const int kk = ks * 8 + 2 * thr;
            uint32_t pa0 = f2tf32(s[ks][0]);
            uint32_t pa1 = f2tf32(s[ks][2]);
            uint32_t pa2 = f2tf32(s[ks][1]);
            uint32_t pa3 = f2tf32(s[ks][3]);
#pragma unroll
            for (int nt = 0; nt < 12; nt++) {
                uint2 vb = *(uint2*)&cV[(nt * 8 + grp) * VP + kk];
                mma_tf32(o[nt][0], o[nt][1], o[nt][2], o[nt][3],
                         pa0, pa1, pa2, pa3, vb.x, vb.y);
            }
        }

        __syncthreads();
        if (kb + 2 < NT) PREF_KV(kb + 2);
    }
#undef PREF_KV

    // epilogue: normalize + tf32-round (feeds cvt-free Wo GEMM)
    float inv0 = 1.f / l0, inv1 = 1.f / l1;
    size_t row0 = ((size_t)b * SEQL + q0 + wr + grp    ) * DIMS + h * HD;
    size_t row1 = ((size_t)b * SEQL + q0 + wr + grp + 8) * DIMS + h * HD;
#pragma unroll
    for (int nt = 0; nt < 12; nt++) {
        int c = nt * 8 + thr * 2;
        *(float2*)(O + row0 + c) = make_float2(
            __uint_as_float(f2tf32(o[nt][0] * inv0)),
            __uint_as_float(f2tf32(o[nt][1] * inv0)));
        *(float2*)(O + row1 + c) = make_float2(
            __uint_as_float(f2tf32(o[nt][2] * inv1)),
            __uint_as_float(f2tf32(o[nt][3] * inv1)));
    }
}

// ---------------------------------------------------------------------------
// Launch
// ---------------------------------------------------------------------------
extern "C" void kernel_launch(void* const* d_in, const int* in_sizes, int n_in,
                              void* d_out, int out_size)
{
    const float* Q_in = (const float*)d_in[0];
    const float* K_in = (const float*)d_in[1];
    const float* V_in = (const float*)d_in[2];
    const float* cq   = (const float*)d_in[3];
    const float* ck   = (const float*)d_in[4];
    const float* Wq   = (const float*)d_in[5];
    const float* Wk   = (const float*)d_in[6];
    const float* Wv   = (const float*)d_in[7];
    const float* Wo   = (const float*)d_in[8];
    float* out = (float*)d_out;

    float *q, *k, *v, *q2, *k2, *att, *wq, *wk, *wv, *wo;
    uint32_t* vt;
    cudaGetSymbolAddress((void**)&q,   g_q);
    cudaGetSymbolAddress((void**)&k,   g_k);
    cudaGetSymbolAddress((void**)&v,   g_v);
    cudaGetSymbolAddress((void**)&q2,  g_q2);
    cudaGetSymbolAddress((void**)&k2,  g_k2);
    cudaGetSymbolAddress((void**)&att, g_att);
    cudaGetSymbolAddress((void**)&vt,  g_vt);
    cudaGetSymbolAddress((void**)&wq,  g_wq);
    cudaGetSymbolAddress((void**)&wk,  g_wk);
    cudaGetSymbolAddress((void**)&wv,  g_wv);
    cudaGetSymbolAddress((void**)&wo,  g_wo);

    cudaFuncSetAttribute(gemm_qkv_kernel, cudaFuncAttributeMaxDynamicSharedMemorySize,
                         GEMM_SMEM_BYTES);
    cudaFuncSetAttribute(gemm_wo_kernel, cudaFuncAttributeMaxDynamicSharedMemorySize,
                         GEMM_SMEM_BYTES);
    cudaFuncSetAttribute(attn_mma_kernel, cudaFuncAttributeMaxDynamicSharedMemorySize,
                         ATTN_SMEM_BYTES);

    round_weights_kernel<<<dim3(DIMS * DIMS / 4 / 256, 4), 256>>>(
        Wq, Wk, Wv, Wo, wq, wk, wv, wo);

    gemm_qkv_kernel<<<dim3(NROWS / TM, DIMS / TN, 3), 256, GEMM_SMEM_BYTES>>>(
        Q_in, K_in, V_in, wq, wk, wv, q, k, v);

    pointwise_kernel<<<dim3(ROPE_BLOCKS, 3), 256>>>(q, q2, cq, k, k2, ck, v, vt);

    attn_mma_kernel<<<dim3(SEQL / BQ, HEADS, BATCH), 128, ATTN_SMEM_BYTES>>>(q2, k2, vt, att);

    gemm_wo_kernel<<<dim3(NROWS / TM, DIMS / TN), 256, GEMM_SMEM_BYTES>>>(att, wo, out);
}